// round 2
// baseline (speedup 1.0000x reference)
#include <cuda_runtime.h>
#include <cstddef>

#define CDIM 256
#define NA_MAX 50000
#define NP_MAX 100000
#define E_MAX  800000

// ---------------- static scratch (allocation-free rule) ----------------
__device__ float g_xa0[NA_MAX * CDIM];
__device__ float g_xa1[NA_MAX * CDIM];
__device__ float g_xp0[NP_MAX * CDIM];
__device__ float g_xp1[NP_MAX * CDIM];
__device__ float g_mw [NP_MAX * CDIM];
__device__ float g_mc [NP_MAX * CDIM];
__device__ float g_ma [NA_MAX * CDIM];
__device__ int   g_off_pw[NP_MAX + 1];
__device__ int   g_off_pc[NP_MAX + 1];
__device__ int   g_off_a [NA_MAX + 1];
__device__ int   g_col_pw[E_MAX];
__device__ int   g_col_pc[E_MAX];
__device__ int   g_col_a [E_MAX];
__device__ int   g_cnt[NP_MAX];
__device__ int   g_cur[NP_MAX];
__device__ float g_Wrp[CDIM * CDIM];
__device__ float g_blp[CDIM];

// ---------------- CSR build ----------------
__global__ void count_kernel(const int* __restrict__ dst, int E, int* __restrict__ cnt) {
    int i = blockIdx.x * blockDim.x + threadIdx.x;
    if (i < E) atomicAdd(&cnt[dst[i]], 1);
}

// single-block exclusive scan -> offsets (off[0]=0, off[i+1]=prefix incl.)
__global__ void scan_kernel(const int* __restrict__ cnt, int* __restrict__ off, int n) {
    __shared__ int wsum[32];
    __shared__ int sbase;
    int tid = threadIdx.x, lane = tid & 31, wid = tid >> 5;
    if (tid == 0) { off[0] = 0; sbase = 0; }
    __syncthreads();
    for (int start = 0; start < n; start += 1024) {
        int i = start + tid;
        int v = (i < n) ? cnt[i] : 0;
        int x = v;
        #pragma unroll
        for (int o = 1; o < 32; o <<= 1) { int y = __shfl_up_sync(0xffffffffu, x, o); if (lane >= o) x += y; }
        if (lane == 31) wsum[wid] = x;
        __syncthreads();
        if (wid == 0) {
            int w = wsum[lane];
            #pragma unroll
            for (int o = 1; o < 32; o <<= 1) { int y = __shfl_up_sync(0xffffffffu, w, o); if (lane >= o) w += y; }
            wsum[lane] = w;
        }
        __syncthreads();
        int incl = x + (wid > 0 ? wsum[wid - 1] : 0);
        int base = sbase;
        if (i < n) off[i + 1] = base + incl;
        __syncthreads();
        if (tid == 1023) sbase = base + incl;
        __syncthreads();
    }
}

__global__ void fill_kernel(const int* __restrict__ src, const int* __restrict__ dst, int E,
                            int* __restrict__ cur, int* __restrict__ col) {
    int i = blockIdx.x * blockDim.x + threadIdx.x;
    if (i < E) {
        int p = atomicAdd(&cur[dst[i]], 1);
        col[p] = src[i];
    }
}

// ---------------- mean aggregation: one warp per destination row ----------------
template <int F>
__global__ void aggregate_mean(const float* __restrict__ xsrc,
                               const int* __restrict__ off, const int* __restrict__ col,
                               float* __restrict__ out, int ndst) {
    int warp = (blockIdx.x * blockDim.x + threadIdx.x) >> 5;
    int lane = threadIdx.x & 31;
    if (warp >= ndst) return;
    constexpr int S = F / 128;   // float4 segments per lane
    float4 acc[S];
    #pragma unroll
    for (int s = 0; s < S; s++) acc[s] = make_float4(0.f, 0.f, 0.f, 0.f);
    int e0 = off[warp], e1 = off[warp + 1];
    for (int e = e0; e < e1; e++) {
        const float4* row = (const float4*)(xsrc + (size_t)col[e] * F);
        #pragma unroll
        for (int s = 0; s < S; s++) {
            float4 v = __ldg(&row[lane + s * 32]);
            acc[s].x += v.x; acc[s].y += v.y; acc[s].z += v.z; acc[s].w += v.w;
        }
    }
    float inv = 1.f / fmaxf((float)(e1 - e0), 1.f);
    float4* orow = (float4*)(out + (size_t)warp * F);
    #pragma unroll
    for (int s = 0; s < S; s++) {
        acc[s].x *= inv; acc[s].y *= inv; acc[s].z *= inv; acc[s].w *= inv;
        orow[lane + s * 32] = acc[s];
    }
}

// ---------------- combine Wr0+Wr2 and biases ----------------
__global__ void combine_kernel(const float* __restrict__ Wa, const float* __restrict__ Wb,
                               const float* __restrict__ ba, const float* __restrict__ bb,
                               float* __restrict__ Wc, float* __restrict__ bc, int KN) {
    int i = blockIdx.x * blockDim.x + threadIdx.x;
    if (i < KN) Wc[i] = Wa[i] + Wb[i];
    if (i < CDIM) bc[i] = ba[i] + bb[i];
}

// ---------------- multi-pair SIMT GEMM: out = sum_i A_i @ W_i + bias [+relu] ----------------
// A_i: [M,K] row-major, W_i: [K,256] row-major, out: [M,256]. BM=BN=128, BK=8, 256 thr, 8x8/thread.
__global__ __launch_bounds__(256, 2)
void gemm_multi(int npair,
                const float* __restrict__ A0, const float* __restrict__ W0,
                const float* __restrict__ A1, const float* __restrict__ W1,
                const float* __restrict__ A2, const float* __restrict__ W2,
                const float* __restrict__ bias, float* __restrict__ out,
                int M, int K, int relu) {
    __shared__ float As[8][132];
    __shared__ float Bs[8][128];
    int tid = threadIdx.x;
    int tx = tid & 15, ty = tid >> 4;
    int rm = ty * 8, rn = tx * 8;
    int bm = blockIdx.x, n0 = blockIdx.y * 128;
    float acc[8][8];
    #pragma unroll
    for (int i = 0; i < 8; i++)
        #pragma unroll
        for (int j = 0; j < 8; j++) acc[i][j] = 0.f;

    int ar = tid >> 1, ac = (tid & 1) * 4;
    int gr = bm * 128 + ar;
    int br = tid >> 5, bc = (tid & 31) * 4;

    for (int p = 0; p < npair; p++) {
        const float* A = (p == 0) ? A0 : ((p == 1) ? A1 : A2);
        const float* W = (p == 0) ? W0 : ((p == 1) ? W1 : W2);
        for (int k0 = 0; k0 < K; k0 += 8) {
            float4 av = make_float4(0.f, 0.f, 0.f, 0.f);
            if (gr < M) av = *(const float4*)(A + (size_t)gr * K + k0 + ac);
            As[ac + 0][ar] = av.x; As[ac + 1][ar] = av.y;
            As[ac + 2][ar] = av.z; As[ac + 3][ar] = av.w;
            *(float4*)&Bs[br][bc] = *(const float4*)(W + (size_t)(k0 + br) * CDIM + n0 + bc);
            __syncthreads();
            #pragma unroll
            for (int kk = 0; kk < 8; kk++) {
                float a[8], b[8];
                *(float4*)&a[0] = *(const float4*)&As[kk][rm];
                *(float4*)&a[4] = *(const float4*)&As[kk][rm + 4];
                *(float4*)&b[0] = *(const float4*)&Bs[kk][rn];
                *(float4*)&b[4] = *(const float4*)&Bs[kk][rn + 4];
                #pragma unroll
                for (int i = 0; i < 8; i++)
                    #pragma unroll
                    for (int j = 0; j < 8; j++) acc[i][j] += a[i] * b[j];
            }
            __syncthreads();
        }
    }
    #pragma unroll
    for (int i = 0; i < 8; i++) {
        int r = bm * 128 + rm + i;
        if (r < M) {
            float t[8];
            #pragma unroll
            for (int j = 0; j < 8; j++) {
                float v = acc[i][j] + bias[n0 + rn + j];
                if (relu) v = fmaxf(v, 0.f);
                t[j] = v;
            }
            float* o = out + (size_t)r * CDIM + n0 + rn;
            *(float4*)o = *(float4*)&t[0];
            *(float4*)(o + 4) = *(float4*)&t[4];
        }
    }
}

// ---------------- decoder init: out[m] = dec_b2 ----------------
__global__ void init_out(float* __restrict__ out, const float* __restrict__ b2, int n) {
    int i = blockIdx.x * blockDim.x + threadIdx.x;
    if (i < n) out[i] = b2[0];
}

// ---------------- fused decoder: gather-GEMM (K=512 via 2 indexed passes) + relu + dot(W2) ----------------
__global__ __launch_bounds__(256, 2)
void decoder_kernel(const float* __restrict__ xa,
                    const int* __restrict__ esrc, const int* __restrict__ edst,
                    const float* __restrict__ W1, const float* __restrict__ b1,
                    const float* __restrict__ W2, float* __restrict__ out, int M) {
    __shared__ float As[8][132];
    __shared__ float Bs[8][128];
    __shared__ float red[128];
    int tid = threadIdx.x;
    int tx = tid & 15, ty = tid >> 4;
    int rm = ty * 8, rn = tx * 8;
    int bm = blockIdx.x, n0 = blockIdx.y * 128;
    float acc[8][8];
    #pragma unroll
    for (int i = 0; i < 8; i++)
        #pragma unroll
        for (int j = 0; j < 8; j++) acc[i][j] = 0.f;

    int ar = tid >> 1, ac = (tid & 1) * 4;
    int gr = bm * 128 + ar;
    int br = tid >> 5, bc = (tid & 31) * 4;

    for (int p = 0; p < 2; p++) {
        const int* idx = p ? edst : esrc;
        int srow = (gr < M) ? idx[gr] : -1;
        const float* W = W1 + (size_t)p * CDIM * CDIM;
        for (int k0 = 0; k0 < CDIM; k0 += 8) {
            float4 av = make_float4(0.f, 0.f, 0.f, 0.f);
            if (srow >= 0) av = *(const float4*)(xa + (size_t)srow * CDIM + k0 + ac);
            As[ac + 0][ar] = av.x; As[ac + 1][ar] = av.y;
            As[ac + 2][ar] = av.z; As[ac + 3][ar] = av.w;
            *(float4*)&Bs[br][bc] = *(const float4*)(W + (size_t)(k0 + br) * CDIM + n0 + bc);
            __syncthreads();
            #pragma unroll
            for (int kk = 0; kk < 8; kk++) {
                float a[8], b[8];
                *(float4*)&a[0] = *(const float4*)&As[kk][rm];
                *(float4*)&a[4] = *(const float4*)&As[kk][rm + 4];
                *(float4*)&b[0] = *(const float4*)&Bs[kk][rn];
                *(float4*)&b[4] = *(const float4*)&Bs[kk][rn + 4];
                #pragma unroll
                for (int i = 0; i < 8; i++)
                    #pragma unroll
                    for (int j = 0; j < 8; j++) acc[i][j] += a[i] * b[j];
            }
            __syncthreads();
        }
    }
    if (tid < 128) red[tid] = 0.f;
    __syncthreads();
    #pragma unroll
    for (int i = 0; i < 8; i++) {
        float partial = 0.f;
        #pragma unroll
        for (int j = 0; j < 8; j++) {
            float v = acc[i][j] + b1[n0 + rn + j];
            v = fmaxf(v, 0.f);
            partial += v * W2[n0 + rn + j];
        }
        atomicAdd(&red[rm + i], partial);
    }
    __syncthreads();
    if (tid < 128) {
        int r = bm * 128 + tid;
        if (r < M) atomicAdd(&out[r], red[tid]);
    }
}

// ---------------- launcher ----------------
extern "C" void kernel_launch(void* const* d_in, const int* in_sizes, int n_in,
                              void* d_out, int out_size) {
    const float* x_author = (const float*)d_in[0];
    const float* x_paper  = (const float*)d_in[1];
    const float* Wl1 = (const float*)d_in[2];
    const float* bl1 = (const float*)d_in[3];
    const float* Wr1 = (const float*)d_in[4];
    const float* Wl  = (const float*)d_in[5];
    const float* bl  = (const float*)d_in[6];
    const float* Wr  = (const float*)d_in[7];
    const float* dW1 = (const float*)d_in[8];
    const float* db1 = (const float*)d_in[9];
    const float* dW2 = (const float*)d_in[10];
    const float* db2 = (const float*)d_in[11];
    const int* wsrc = (const int*)d_in[12];
    const int* wdst = (const int*)d_in[13];
    const int* csrc = (const int*)d_in[14];
    const int* cdst = (const int*)d_in[15];
    const int* esrc = (const int*)d_in[16];
    const int* edst = (const int*)d_in[17];
    float* out = (float*)d_out;

    int Na = in_sizes[0] / 128;
    int Np = in_sizes[1] / 128;
    int E  = in_sizes[12];
    int EL = in_sizes[16];

    float *xa0, *xa1, *xp0, *xp1, *mw, *mc, *ma, *Wrp, *blp;
    int *off_pw, *off_pc, *off_a, *col_pw, *col_pc, *col_a, *cnt, *cur;
    cudaGetSymbolAddress((void**)&xa0, g_xa0);
    cudaGetSymbolAddress((void**)&xa1, g_xa1);
    cudaGetSymbolAddress((void**)&xp0, g_xp0);
    cudaGetSymbolAddress((void**)&xp1, g_xp1);
    cudaGetSymbolAddress((void**)&mw,  g_mw);
    cudaGetSymbolAddress((void**)&mc,  g_mc);
    cudaGetSymbolAddress((void**)&ma,  g_ma);
    cudaGetSymbolAddress((void**)&Wrp, g_Wrp);
    cudaGetSymbolAddress((void**)&blp, g_blp);
    cudaGetSymbolAddress((void**)&off_pw, g_off_pw);
    cudaGetSymbolAddress((void**)&off_pc, g_off_pc);
    cudaGetSymbolAddress((void**)&off_a,  g_off_a);
    cudaGetSymbolAddress((void**)&col_pw, g_col_pw);
    cudaGetSymbolAddress((void**)&col_pc, g_col_pc);
    cudaGetSymbolAddress((void**)&col_a,  g_col_a);
    cudaGetSymbolAddress((void**)&cnt, g_cnt);
    cudaGetSymbolAddress((void**)&cur, g_cur);

    int egrid = (E + 255) / 256;

    // ---- CSR build (3 edge maps) ----
    // papers <- authors via writes
    cudaMemsetAsync(cnt, 0, Np * sizeof(int));
    count_kernel<<<egrid, 256>>>(wdst, E, cnt);
    scan_kernel<<<1, 1024>>>(cnt, off_pw, Np);
    cudaMemcpyAsync(cur, off_pw, Np * sizeof(int), cudaMemcpyDeviceToDevice);
    fill_kernel<<<egrid, 256>>>(wsrc, wdst, E, cur, col_pw);
    // papers <- papers via cites
    cudaMemsetAsync(cnt, 0, Np * sizeof(int));
    count_kernel<<<egrid, 256>>>(cdst, E, cnt);
    scan_kernel<<<1, 1024>>>(cnt, off_pc, Np);
    cudaMemcpyAsync(cur, off_pc, Np * sizeof(int), cudaMemcpyDeviceToDevice);
    fill_kernel<<<egrid, 256>>>(csrc, cdst, E, cur, col_pc);
    // authors <- papers via writes reversed
    cudaMemsetAsync(cnt, 0, Na * sizeof(int));
    count_kernel<<<egrid, 256>>>(wsrc, E, cnt);
    scan_kernel<<<1, 1024>>>(cnt, off_a, Na);
    cudaMemcpyAsync(cur, off_a, Na * sizeof(int), cudaMemcpyDeviceToDevice);
    fill_kernel<<<egrid, 256>>>(wdst, wsrc, E, cur, col_a);

    const float* in_a = x_author;
    const float* in_p = x_paper;
    float* outs_a[4] = { xa0, xa1, xa0, xa1 };
    float* outs_p[4] = { xp0, xp1, xp0, xp1 };

    for (int l = 0; l < 4; l++) {
        int Kin = (l == 0) ? 128 : 256;
        if (Kin == 128) {
            aggregate_mean<128><<<(Np + 7) / 8, 256>>>(in_a, off_pw, col_pw, mw, Np);
            aggregate_mean<128><<<(Np + 7) / 8, 256>>>(in_p, off_pc, col_pc, mc, Np);
            aggregate_mean<128><<<(Na + 7) / 8, 256>>>(in_p, off_a, col_a, ma, Na);
        } else {
            aggregate_mean<256><<<(Np + 7) / 8, 256>>>(in_a, off_pw, col_pw, mw, Np);
            aggregate_mean<256><<<(Np + 7) / 8, 256>>>(in_p, off_pc, col_pc, mc, Np);
            aggregate_mean<256><<<(Na + 7) / 8, 256>>>(in_p, off_a, col_a, ma, Na);
        }
        const float *wl0, *wl1e, *wl2, *wr0, *wr1e, *wr2, *b0, *b1e, *b2e;
        if (l == 0) {
            wl0 = Wl1;               wl1e = Wl1 + 128 * 256;  wl2 = Wl1 + 2 * 128 * 256;
            wr0 = Wr1;               wr1e = Wr1 + 128 * 256;  wr2 = Wr1 + 2 * 128 * 256;
            b0  = bl1;               b1e  = bl1 + 256;        b2e = bl1 + 512;
        } else {
            int li = l - 1;
            wl0  = Wl + (size_t)(li * 3 + 0) * 65536;
            wl1e = Wl + (size_t)(li * 3 + 1) * 65536;
            wl2  = Wl + (size_t)(li * 3 + 2) * 65536;
            wr0  = Wr + (size_t)(li * 3 + 0) * 65536;
            wr1e = Wr + (size_t)(li * 3 + 1) * 65536;
            wr2  = Wr + (size_t)(li * 3 + 2) * 65536;
            b0   = bl + (size_t)(li * 3 + 0) * 256;
            b1e  = bl + (size_t)(li * 3 + 1) * 256;
            b2e  = bl + (size_t)(li * 3 + 2) * 256;
        }
        combine_kernel<<<(Kin * 256 + 255) / 256, 256>>>(wr0, wr2, b0, b2e, Wrp, blp, Kin * 256);
        int relu = (l < 3) ? 1 : 0;
        gemm_multi<<<dim3((Np + 127) / 128, 2), 256>>>(3, mw, wl0, mc, wl2, in_p, Wrp,
                                                       blp, outs_p[l], Np, Kin, relu);
        gemm_multi<<<dim3((Na + 127) / 128, 2), 256>>>(2, ma, wl1e, in_a, wr1e,
                                                       (const float*)nullptr, (const float*)nullptr,
                                                       b1e, outs_a[l], Na, Kin, relu);
        in_a = outs_a[l];
        in_p = outs_p[l];
    }

    init_out<<<(EL + 255) / 256, 256>>>(out, db2, EL);
    decoder_kernel<<<dim3((EL + 127) / 128, 2), 256>>>(in_a, esrc, edst, dW1, db1, dW2, out, EL);
}

// round 4
// speedup vs baseline: 1.6979x; 1.6979x over previous
#include <cuda_runtime.h>
#include <cuda_bf16.h>
#include <cstdint>
#include <cstddef>

#define CDIM 256
#define NA_MAX 50000
#define NP_MAX 100000
#define E_MAX  800000
#define WSTRIDE 65536   // 256*256 slot stride for transposed weights
#define NSLOT 22        // 4 layers * 5 + 2 decoder halves

// ---------------- static scratch (allocation-free rule) ----------------
__device__ __nv_bfloat16 g_xaH0[NA_MAX * CDIM], g_xaL0[NA_MAX * CDIM];
__device__ __nv_bfloat16 g_xaH1[NA_MAX * CDIM], g_xaL1[NA_MAX * CDIM];
__device__ __nv_bfloat16 g_xpH0[NP_MAX * CDIM], g_xpL0[NP_MAX * CDIM];
__device__ __nv_bfloat16 g_xpH1[NP_MAX * CDIM], g_xpL1[NP_MAX * CDIM];
__device__ __nv_bfloat16 g_mwH [NP_MAX * CDIM], g_mwL [NP_MAX * CDIM];
__device__ __nv_bfloat16 g_mcH [NP_MAX * CDIM], g_mcL [NP_MAX * CDIM];
__device__ __nv_bfloat16 g_maH [NA_MAX * CDIM], g_maL [NA_MAX * CDIM];
__device__ __nv_bfloat16 g_xaiH[NA_MAX * 128],  g_xaiL[NA_MAX * 128];
__device__ __nv_bfloat16 g_xpiH[NP_MAX * 128],  g_xpiL[NP_MAX * 128];
__device__ __nv_bfloat16 g_wtH[NSLOT * WSTRIDE], g_wtL[NSLOT * WSTRIDE];
__device__ float g_blp[4 * CDIM];
__device__ int g_off_pw[NP_MAX + 1], g_off_pc[NP_MAX + 1], g_off_a[NA_MAX + 1];
__device__ int g_col_pw[E_MAX], g_col_pc[E_MAX], g_col_a[E_MAX];
__device__ int g_cnt[NP_MAX], g_cur[NP_MAX];

// ================= CSR build =================
__global__ void count_kernel(const int* __restrict__ dst, int E, int* __restrict__ cnt) {
    int i = blockIdx.x * blockDim.x + threadIdx.x;
    if (i < E) atomicAdd(&cnt[dst[i]], 1);
}
__global__ void scan_kernel(const int* __restrict__ cnt, int* __restrict__ off, int n) {
    __shared__ int wsum[32];
    __shared__ int sbase;
    int tid = threadIdx.x, lane = tid & 31, wid = tid >> 5;
    if (tid == 0) { off[0] = 0; sbase = 0; }
    __syncthreads();
    for (int start = 0; start < n; start += 1024) {
        int i = start + tid;
        int v = (i < n) ? cnt[i] : 0;
        int x = v;
        #pragma unroll
        for (int o = 1; o < 32; o <<= 1) { int y = __shfl_up_sync(0xffffffffu, x, o); if (lane >= o) x += y; }
        if (lane == 31) wsum[wid] = x;
        __syncthreads();
        if (wid == 0) {
            int w = wsum[lane];
            #pragma unroll
            for (int o = 1; o < 32; o <<= 1) { int y = __shfl_up_sync(0xffffffffu, w, o); if (lane >= o) w += y; }
            wsum[lane] = w;
        }
        __syncthreads();
        int incl = x + (wid > 0 ? wsum[wid - 1] : 0);
        int base = sbase;
        if (i < n) off[i + 1] = base + incl;
        __syncthreads();
        if (tid == 1023) sbase = base + incl;
        __syncthreads();
    }
}
__global__ void fill_kernel(const int* __restrict__ src, const int* __restrict__ dst, int E,
                            int* __restrict__ cur, int* __restrict__ col) {
    int i = blockIdx.x * blockDim.x + threadIdx.x;
    if (i < E) {
        int p = atomicAdd(&cur[dst[i]], 1);
        col[p] = src[i];
    }
}

// ================= conversions =================
static __device__ __forceinline__ void split2(float v, __nv_bfloat16& h, __nv_bfloat16& l) {
    h = __float2bfloat16(v);
    l = __float2bfloat16(v - __bfloat162float(h));
}
__global__ void split_kernel(const float* __restrict__ x, __nv_bfloat16* __restrict__ h,
                             __nv_bfloat16* __restrict__ l, int n) {
    int i = blockIdx.x * blockDim.x + threadIdx.x;
    if (i < n) { __nv_bfloat16 hh, ll; split2(x[i], hh, ll); h[i] = hh; l[i] = ll; }
}
// W [K,256] fp32 (+optional add) -> transposed split [256,K] bf16
__global__ void wt_convert(const float* __restrict__ A, const float* __restrict__ B, int K,
                           __nv_bfloat16* __restrict__ oh, __nv_bfloat16* __restrict__ ol) {
    int i = blockIdx.x * blockDim.x + threadIdx.x;
    if (i >= 256 * K) return;
    int k = i % K, n = i / K;
    float v = A[k * 256 + n];
    if (B) v += B[k * 256 + n];
    __nv_bfloat16 h, l; split2(v, h, l);
    oh[i] = h; ol[i] = l;
}
__global__ void bias_comb(const float* __restrict__ a, const float* __restrict__ b, float* __restrict__ o) {
    int i = threadIdx.x;
    o[i] = a[i] + b[i];
}

// ================= mean aggregation on hi/lo bf16, warp per row =================
static __device__ __forceinline__ void acc_pair(float* acc, uint32_t uh, uint32_t ul, int base) {
    __nv_bfloat162 h = *reinterpret_cast<__nv_bfloat162*>(&uh);
    __nv_bfloat162 l = *reinterpret_cast<__nv_bfloat162*>(&ul);
    float2 fh = __bfloat1622float2(h), fl = __bfloat1622float2(l);
    acc[base + 0] += fh.x + fl.x;
    acc[base + 1] += fh.y + fl.y;
}
template <int F>
__global__ void aggregate_mean_bf(const __nv_bfloat16* __restrict__ sh, const __nv_bfloat16* __restrict__ sl,
                                  const int* __restrict__ off, const int* __restrict__ col,
                                  __nv_bfloat16* __restrict__ dh, __nv_bfloat16* __restrict__ dl, int ndst) {
    int warp = (blockIdx.x * blockDim.x + threadIdx.x) >> 5;
    int lane = threadIdx.x & 31;
    if (warp >= ndst) return;
    constexpr int C = F / 32;  // cols per lane: 8 (F=256) or 4 (F=128)
    float acc[C];
    #pragma unroll
    for (int c = 0; c < C; c++) acc[c] = 0.f;
    int e0 = off[warp], e1 = off[warp + 1];
    for (int e = e0; e < e1; e++) {
        size_t base = (size_t)col[e] * F + lane * C;
        if (C == 8) {
            uint4 a = *(const uint4*)(sh + base);
            uint4 b = *(const uint4*)(sl + base);
            acc_pair(acc, a.x, b.x, 0); acc_pair(acc, a.y, b.y, 2);
            acc_pair(acc, a.z, b.z, 4); acc_pair(acc, a.w, b.w, 6);
        } else {
            uint2 a = *(const uint2*)(sh + base);
            uint2 b = *(const uint2*)(sl + base);
            acc_pair(acc, a.x, b.x, 0); acc_pair(acc, a.y, b.y, 2);
        }
    }
    float inv = 1.f / fmaxf((float)(e1 - e0), 1.f);
    __nv_bfloat162 H[C / 2], L[C / 2];
    #pragma unroll
    for (int c = 0; c < C / 2; c++) {
        __nv_bfloat16 h0, l0, h1, l1;
        split2(acc[2 * c + 0] * inv, h0, l0);
        split2(acc[2 * c + 1] * inv, h1, l1);
        H[c].x = h0; H[c].y = h1; L[c].x = l0; L[c].y = l1;
    }
    size_t ob = (size_t)warp * F + lane * C;
    if (C == 8) {
        *(uint4*)(dh + ob) = *(uint4*)H;
        *(uint4*)(dl + ob) = *(uint4*)L;
    } else {
        *(uint2*)(dh + ob) = *(uint2*)H;
        *(uint2*)(dl + ob) = *(uint2*)L;
    }
}

// ================= mma.sync helpers =================
static __device__ __forceinline__ void mma16816(float* c, const uint32_t* a, const uint32_t* b) {
    asm volatile(
        "mma.sync.aligned.m16n8k16.row.col.f32.bf16.bf16.f32 "
        "{%0,%1,%2,%3}, {%4,%5,%6,%7}, {%8,%9}, {%0,%1,%2,%3};"
        : "+f"(c[0]), "+f"(c[1]), "+f"(c[2]), "+f"(c[3])
        : "r"(a[0]), "r"(a[1]), "r"(a[2]), "r"(a[3]), "r"(b[0]), "r"(b[1]));
}
static __device__ __forceinline__ uint32_t lds32(const __nv_bfloat16* s, int idx) {
    return *(const uint32_t*)(s + idx);
}

#define SPAD 40  // smem row stride in bf16 (32 + 8 pad): conflict-free for fills & frag loads

// ================= mma.sync GEMM: out(hi/lo) = relu?(sum_p A_p@W_p^T + bias) =================
// A_p: [M,K] bf16 hi/lo row-major; B_p: [256,K] bf16 hi/lo (pre-transposed weights).
// CTA 128x128, 512 thr (16 warps 4x4), warp tile 32x32, BK=32, 3-pass hi/lo split.
__global__ __launch_bounds__(512, 1)
void gemm_mma(int npair,
              const __nv_bfloat16* __restrict__ A0h, const __nv_bfloat16* __restrict__ A0l,
              const __nv_bfloat16* __restrict__ B0h, const __nv_bfloat16* __restrict__ B0l,
              const __nv_bfloat16* __restrict__ A1h, const __nv_bfloat16* __restrict__ A1l,
              const __nv_bfloat16* __restrict__ B1h, const __nv_bfloat16* __restrict__ B1l,
              const __nv_bfloat16* __restrict__ A2h, const __nv_bfloat16* __restrict__ A2l,
              const __nv_bfloat16* __restrict__ B2h, const __nv_bfloat16* __restrict__ B2l,
              const float* __restrict__ bias,
              __nv_bfloat16* __restrict__ oh, __nv_bfloat16* __restrict__ ol,
              int M, int K, int relu) {
    __shared__ __nv_bfloat16 sAh[128 * SPAD], sAl[128 * SPAD];
    __shared__ __nv_bfloat16 sBh[128 * SPAD], sBl[128 * SPAD];
    int tid = threadIdx.x, lane = tid & 31, warp = tid >> 5;
    int wm = warp >> 2, wn = warp & 3;
    int m0 = blockIdx.x * 128, n0 = blockIdx.y * 128;
    float acc[2][4][4];
    #pragma unroll
    for (int i = 0; i < 2; i++)
        #pragma unroll
        for (int j = 0; j < 4; j++)
            #pragma unroll
            for (int q = 0; q < 4; q++) acc[i][j][q] = 0.f;

    int cpp = K >> 5;
    int total = npair * cpp;
    int lrow = tid >> 2, lkq = (tid & 3) * 8;
    bool aval = (m0 + lrow) < M;

    uint4 va_h, va_l, vb_h, vb_l;
    auto fetch = [&](int t) {
        int p = t / cpp, kc = t - p * cpp;
        const __nv_bfloat16 *Ah, *Al, *Bh, *Bl;
        if (p == 0)      { Ah = A0h; Al = A0l; Bh = B0h; Bl = B0l; }
        else if (p == 1) { Ah = A1h; Al = A1l; Bh = B1h; Bl = B1l; }
        else             { Ah = A2h; Al = A2l; Bh = B2h; Bl = B2l; }
        size_t ao = (size_t)(m0 + lrow) * K + kc * 32 + lkq;
        size_t bo = (size_t)(n0 + lrow) * K + kc * 32 + lkq;
        if (aval) {
            va_h = *(const uint4*)(Ah + ao);
            va_l = *(const uint4*)(Al + ao);
        } else {
            va_h = make_uint4(0, 0, 0, 0);
            va_l = make_uint4(0, 0, 0, 0);
        }
        vb_h = *(const uint4*)(Bh + bo);
        vb_l = *(const uint4*)(Bl + bo);
    };
    fetch(0);
    for (int t = 0; t < total; t++) {
        int so = lrow * SPAD + lkq;
        *(uint4*)(sAh + so) = va_h; *(uint4*)(sAl + so) = va_l;
        *(uint4*)(sBh + so) = vb_h; *(uint4*)(sBl + so) = vb_l;
        __syncthreads();
        if (t + 1 < total) fetch(t + 1);
        #pragma unroll
        for (int ks = 0; ks < 2; ks++) {
            int k = ks * 16 + (lane & 3) * 2;
            int r = lane >> 2;
            uint32_t ah[2][4], al[2][4], bh[4][2], bl[4][2];
            #pragma unroll
            for (int i = 0; i < 2; i++) {
                int m = wm * 32 + i * 16 + r;
                ah[i][0] = lds32(sAh, m * SPAD + k);       ah[i][1] = lds32(sAh, (m + 8) * SPAD + k);
                ah[i][2] = lds32(sAh, m * SPAD + k + 8);   ah[i][3] = lds32(sAh, (m + 8) * SPAD + k + 8);
                al[i][0] = lds32(sAl, m * SPAD + k);       al[i][1] = lds32(sAl, (m + 8) * SPAD + k);
                al[i][2] = lds32(sAl, m * SPAD + k + 8);   al[i][3] = lds32(sAl, (m + 8) * SPAD + k + 8);
            }
            #pragma unroll
            for (int j = 0; j < 4; j++) {
                int n = wn * 32 + j * 8 + r;
                bh[j][0] = lds32(sBh, n * SPAD + k); bh[j][1] = lds32(sBh, n * SPAD + k + 8);
                bl[j][0] = lds32(sBl, n * SPAD + k); bl[j][1] = lds32(sBl, n * SPAD + k + 8);
            }
            #pragma unroll
            for (int i = 0; i < 2; i++)
                #pragma unroll
                for (int j = 0; j < 4; j++) {
                    mma16816(acc[i][j], ah[i], bh[j]);
                    mma16816(acc[i][j], ah[i], bl[j]);
                    mma16816(acc[i][j], al[i], bh[j]);
                }
        }
        __syncthreads();
    }
    // epilogue: bias + relu + split -> hi/lo bf16
    #pragma unroll
    for (int i = 0; i < 2; i++) {
        int r0 = m0 + wm * 32 + i * 16 + (lane >> 2);
        #pragma unroll
        for (int j = 0; j < 4; j++) {
            int c = n0 + wn * 32 + j * 8 + (lane & 3) * 2;
            float b0 = __ldg(&bias[c]), b1v = __ldg(&bias[c + 1]);
            if (r0 < M) {
                float v0 = acc[i][j][0] + b0, v1 = acc[i][j][1] + b1v;
                if (relu) { v0 = fmaxf(v0, 0.f); v1 = fmaxf(v1, 0.f); }
                __nv_bfloat162 H, L;
                split2(v0, H.x, L.x); split2(v1, H.y, L.y);
                *(uint32_t*)(oh + (size_t)r0 * 256 + c) = *(uint32_t*)&H;
                *(uint32_t*)(ol + (size_t)r0 * 256 + c) = *(uint32_t*)&L;
            }
            if (r0 + 8 < M) {
                float v0 = acc[i][j][2] + b0, v1 = acc[i][j][3] + b1v;
                if (relu) { v0 = fmaxf(v0, 0.f); v1 = fmaxf(v1, 0.f); }
                __nv_bfloat162 H, L;
                split2(v0, H.x, L.x); split2(v1, H.y, L.y);
                *(uint32_t*)(oh + (size_t)(r0 + 8) * 256 + c) = *(uint32_t*)&H;
                *(uint32_t*)(ol + (size_t)(r0 + 8) * 256 + c) = *(uint32_t*)&L;
            }
        }
    }
}

// ================= decoder init =================
__global__ void init_out(float* __restrict__ out, const float* __restrict__ b2, int n) {
    int i = blockIdx.x * blockDim.x + threadIdx.x;
    if (i < n) out[i] = b2[0];
}

// ================= fused decoder: gather-A mma GEMM + relu-dot epilogue =================
__global__ __launch_bounds__(512, 1)
void decoder_mma(const __nv_bfloat16* __restrict__ xah, const __nv_bfloat16* __restrict__ xal,
                 const int* __restrict__ esrc, const int* __restrict__ edst,
                 const __nv_bfloat16* __restrict__ B0h, const __nv_bfloat16* __restrict__ B0l,
                 const __nv_bfloat16* __restrict__ B1h, const __nv_bfloat16* __restrict__ B1l,
                 const float* __restrict__ b1, const float* __restrict__ W2,
                 float* __restrict__ out, int M) {
    __shared__ __nv_bfloat16 sAh[128 * SPAD], sAl[128 * SPAD];
    __shared__ __nv_bfloat16 sBh[128 * SPAD], sBl[128 * SPAD];
    __shared__ float red[128];
    int tid = threadIdx.x, lane = tid & 31, warp = tid >> 5;
    int wm = warp >> 2, wn = warp & 3;
    int m0 = blockIdx.x * 128, n0 = blockIdx.y * 128;
    float acc[2][4][4];
    #pragma unroll
    for (int i = 0; i < 2; i++)
        #pragma unroll
        for (int j = 0; j < 4; j++)
            #pragma unroll
            for (int q = 0; q < 4; q++) acc[i][j][q] = 0.f;

    int lrow = tid >> 2, lkq = (tid & 3) * 8;
    bool aval = (m0 + lrow) < M;
    int a0i = aval ? __ldg(&esrc[m0 + lrow]) : 0;
    int a1i = aval ? __ldg(&edst[m0 + lrow]) : 0;
    if (tid < 128) red[tid] = 0.f;

    uint4 va_h, va_l, vb_h, vb_l;
    auto fetch = [&](int t) {
        int p = t >> 3, kc = t & 7;
        const __nv_bfloat16* Bh = p ? B1h : B0h;
        const __nv_bfloat16* Bl = p ? B1l : B0l;
        int ar = p ? a1i : a0i;
        size_t ao = (size_t)ar * 256 + kc * 32 + lkq;
        size_t bo = (size_t)(n0 + lrow) * 256 + kc * 32 + lkq;
        if (aval) {
            va_h = *(const uint4*)(xah + ao);
            va_l = *(const uint4*)(xal + ao);
        } else {
            va_h = make_uint4(0, 0, 0, 0);
            va_l = make_uint4(0, 0, 0, 0);
        }
        vb_h = *(const uint4*)(Bh + bo);
        vb_l = *(const uint4*)(Bl + bo);
    };
    fetch(0);
    for (int t = 0; t < 16; t++) {
        int so = lrow * SPAD + lkq;
        *(uint4*)(sAh + so) = va_h; *(uint4*)(sAl + so) = va_l;
        *(uint4*)(sBh + so) = vb_h; *(uint4*)(sBl + so) = vb_l;
        __syncthreads();
        if (t + 1 < 16) fetch(t + 1);
        #pragma unroll
        for (int ks = 0; ks < 2; ks++) {
            int k = ks * 16 + (lane & 3) * 2;
            int r = lane >> 2;
            uint32_t ah[2][4], al[2][4], bh[4][2], bl[4][2];
            #pragma unroll
            for (int i = 0; i < 2; i++) {
                int m = wm * 32 + i * 16 + r;
                ah[i][0] = lds32(sAh, m * SPAD + k);       ah[i][1] = lds32(sAh, (m + 8) * SPAD + k);
                ah[i][2] = lds32(sAh, m * SPAD + k + 8);   ah[i][3] = lds32(sAh, (m + 8) * SPAD + k + 8);
                al[i][0] = lds32(sAl, m * SPAD + k);       al[i][1] = lds32(sAl, (m + 8) * SPAD + k);
                al[i][2] = lds32(sAl, m * SPAD + k + 8);   al[i][3] = lds32(sAl, (m + 8) * SPAD + k + 8);
            }
            #pragma unroll
            for (int j = 0; j < 4; j++) {
                int n = wn * 32 + j * 8 + r;
                bh[j][0] = lds32(sBh, n * SPAD + k); bh[j][1] = lds32(sBh, n * SPAD + k + 8);
                bl[j][0] = lds32(sBl, n * SPAD + k); bl[j][1] = lds32(sBl, n * SPAD + k + 8);
            }
            #pragma unroll
            for (int i = 0; i < 2; i++)
                #pragma unroll
                for (int j = 0; j < 4; j++) {
                    mma16816(acc[i][j], ah[i], bh[j]);
                    mma16816(acc[i][j], ah[i], bl[j]);
                    mma16816(acc[i][j], al[i], bh[j]);
                }
        }
        __syncthreads();
    }
    // epilogue: relu(acc + b1) dot W2, reduce per row
    #pragma unroll
    for (int i = 0; i < 2; i++) {
        int rl = wm * 32 + i * 16 + (lane >> 2);
        float p0 = 0.f, p1 = 0.f;
        #pragma unroll
        for (int j = 0; j < 4; j++) {
            int c = n0 + wn * 32 + j * 8 + (lane & 3) * 2;
            float b0 = __ldg(&b1[c]), b1v = __ldg(&b1[c + 1]);
            float w0 = __ldg(&W2[c]), w1 = __ldg(&W2[c + 1]);
            p0 += fmaxf(acc[i][j][0] + b0, 0.f) * w0 + fmaxf(acc[i][j][1] + b1v, 0.f) * w1;
            p1 += fmaxf(acc[i][j][2] + b0, 0.f) * w0 + fmaxf(acc[i][j][3] + b1v, 0.f) * w1;
        }
        atomicAdd(&red[rl], p0);
        atomicAdd(&red[rl + 8], p1);
    }
    __syncthreads();
    if (tid < 128 && m0 + tid < M) atomicAdd(&out[m0 + tid], red[tid]);
}

// ================= launcher =================
extern "C" void kernel_launch(void* const* d_in, const int* in_sizes, int n_in,
                              void* d_out, int out_size) {
    const float* x_author = (const float*)d_in[0];
    const float* x_paper  = (const float*)d_in[1];
    const float* Wl1 = (const float*)d_in[2];
    const float* bl1 = (const float*)d_in[3];
    const float* Wr1 = (const float*)d_in[4];
    const float* Wl  = (const float*)d_in[5];
    const float* bl  = (const float*)d_in[6];
    const float* Wr  = (const float*)d_in[7];
    const float* dW1 = (const float*)d_in[8];
    const float* db1 = (const float*)d_in[9];
    const float* dW2 = (const float*)d_in[10];
    const float* db2 = (const float*)d_in[11];
    const int* wsrc = (const int*)d_in[12];
    const int* wdst = (const int*)d_in[13];
    const int* csrc = (const int*)d_in[14];
    const int* cdst = (const int*)d_in[15];
    const int* esrc = (const int*)d_in[16];
    const int* edst = (const int*)d_in[17];
    float* out = (float*)d_out;

    int Na = in_sizes[0] / 128;
    int Np = in_sizes[1] / 128;
    int E  = in_sizes[12];
    int EL = in_sizes[16];

    __nv_bfloat16 *xaH[2], *xaL[2], *xpH[2], *xpL[2];
    __nv_bfloat16 *mwH, *mwL, *mcH, *mcL, *maH, *maL, *xaiH, *xaiL, *xpiH, *xpiL, *wtH, *wtL;
    float* blp;
    int *off_pw, *off_pc, *off_a, *col_pw, *col_pc, *col_a, *cnt, *cur;
    cudaGetSymbolAddress((void**)&xaH[0], g_xaH0); cudaGetSymbolAddress((void**)&xaL[0], g_xaL0);
    cudaGetSymbolAddress((void**)&xaH[1], g_xaH1); cudaGetSymbolAddress((void**)&xaL[1], g_xaL1);
    cudaGetSymbolAddress((void**)&xpH[0], g_xpH0); cudaGetSymbolAddress((void**)&xpL[0], g_xpL0);
    cudaGetSymbolAddress((void**)&xpH[1], g_xpH1); cudaGetSymbolAddress((void**)&xpL[1], g_xpL1);
    cudaGetSymbolAddress((void**)&mwH, g_mwH); cudaGetSymbolAddress((void**)&mwL, g_mwL);
    cudaGetSymbolAddress((void**)&mcH, g_mcH); cudaGetSymbolAddress((void**)&mcL, g_mcL);
    cudaGetSymbolAddress((void**)&maH, g_maH); cudaGetSymbolAddress((void**)&maL, g_maL);
    cudaGetSymbolAddress((void**)&xaiH, g_xaiH); cudaGetSymbolAddress((void**)&xaiL, g_xaiL);
    cudaGetSymbolAddress((void**)&xpiH, g_xpiH); cudaGetSymbolAddress((void**)&xpiL, g_xpiL);
    cudaGetSymbolAddress((void**)&wtH, g_wtH); cudaGetSymbolAddress((void**)&wtL, g_wtL);
    cudaGetSymbolAddress((void**)&blp, g_blp);
    cudaGetSymbolAddress((void**)&off_pw, g_off_pw); cudaGetSymbolAddress((void**)&off_pc, g_off_pc);
    cudaGetSymbolAddress((void**)&off_a, g_off_a);
    cudaGetSymbolAddress((void**)&col_pw, g_col_pw); cudaGetSymbolAddress((void**)&col_pc, g_col_pc);
    cudaGetSymbolAddress((void**)&col_a, g_col_a);
    cudaGetSymbolAddress((void**)&cnt, g_cnt); cudaGetSymbolAddress((void**)&cur, g_cur);

    int egrid = (E + 255) / 256;

    // ---- CSR build ----
    cudaMemsetAsync(cnt, 0, Np * sizeof(int));
    count_kernel<<<egrid, 256>>>(wdst, E, cnt);
    scan_kernel<<<1, 1024>>>(cnt, off_pw, Np);
    cudaMemcpyAsync(cur, off_pw, Np * sizeof(int), cudaMemcpyDeviceToDevice);
    fill_kernel<<<egrid, 256>>>(wsrc, wdst, E, cur, col_pw);

    cudaMemsetAsync(cnt, 0, Np * sizeof(int));
    count_kernel<<<egrid, 256>>>(cdst, E, cnt);
    scan_kernel<<<1, 1024>>>(cnt, off_pc, Np);
    cudaMemcpyAsync(cur, off_pc, Np * sizeof(int), cudaMemcpyDeviceToDevice);
    fill_kernel<<<egrid, 256>>>(csrc, cdst, E, cur, col_pc);

    cudaMemsetAsync(cnt, 0, Na * sizeof(int));
    count_kernel<<<egrid, 256>>>(wsrc, E, cnt);
    scan_kernel<<<1, 1024>>>(cnt, off_a, Na);
    cudaMemcpyAsync(cur, off_a, Na * sizeof(int), cudaMemcpyDeviceToDevice);
    fill_kernel<<<egrid, 256>>>(wdst, wsrc, E, cur, col_a);

    // ---- input split to hi/lo bf16 ----
    split_kernel<<<(Na * 128 + 255) / 256, 256>>>(x_author, xaiH, xaiL, Na * 128);
    split_kernel<<<(Np * 128 + 255) / 256, 256>>>(x_paper, xpiH, xpiL, Np * 128);

    // ---- weight transpose + split ----
    for (int l = 0; l < 4; l++) {
        int K = (l == 0) ? 128 : 256;
        const float *wl0, *wl1e, *wl2, *wr0, *wr1e, *wr2, *b0, *b2e;
        if (l == 0) {
            wl0 = Wl1; wl1e = Wl1 + 128 * 256; wl2 = Wl1 + 2 * 128 * 256;
            wr0 = Wr1; wr1e = Wr1 + 128 * 256; wr2 = Wr1 + 2 * 128 * 256;
            b0 = bl1; b2e = bl1 + 512;
        } else {
            int li = l - 1;
            wl0  = Wl + (size_t)(li * 3 + 0) * 65536;
            wl1e = Wl + (size_t)(li * 3 + 1) * 65536;
            wl2  = Wl + (size_t)(li * 3 + 2) * 65536;
            wr0  = Wr + (size_t)(li * 3 + 0) * 65536;
            wr1e = Wr + (size_t)(li * 3 + 1) * 65536;
            wr2  = Wr + (size_t)(li * 3 + 2) * 65536;
            b0   = bl + (size_t)(li * 3 + 0) * 256;
            b2e  = bl + (size_t)(li * 3 + 2) * 256;
        }
        int g = (256 * K + 255) / 256;
        int s = l * 5;
        wt_convert<<<g, 256>>>(wl0, (const float*)nullptr, K, wtH + (size_t)(s + 0) * WSTRIDE, wtL + (size_t)(s + 0) * WSTRIDE);
        wt_convert<<<g, 256>>>(wl2, (const float*)nullptr, K, wtH + (size_t)(s + 1) * WSTRIDE, wtL + (size_t)(s + 1) * WSTRIDE);
        wt_convert<<<g, 256>>>(wr0, wr2,                  K, wtH + (size_t)(s + 2) * WSTRIDE, wtL + (size_t)(s + 2) * WSTRIDE);
        wt_convert<<<g, 256>>>(wl1e, (const float*)nullptr, K, wtH + (size_t)(s + 3) * WSTRIDE, wtL + (size_t)(s + 3) * WSTRIDE);
        wt_convert<<<g, 256>>>(wr1e, (const float*)nullptr, K, wtH + (size_t)(s + 4) * WSTRIDE, wtL + (size_t)(s + 4) * WSTRIDE);
        bias_comb<<<1, 256>>>(b0, b2e, blp + l * 256);
    }
    wt_convert<<<256, 256>>>(dW1,             (const float*)nullptr, 256, wtH + (size_t)20 * WSTRIDE, wtL + (size_t)20 * WSTRIDE);
    wt_convert<<<256, 256>>>(dW1 + 256 * 256, (const float*)nullptr, 256, wtH + (size_t)21 * WSTRIDE, wtL + (size_t)21 * WSTRIDE);

    // ---- layers ----
    const __nv_bfloat16 *iaH = xaiH, *iaL = xaiL, *ipH = xpiH, *ipL = xpiL;
    dim3 gp((Np + 127) / 128, 2), ga((Na + 127) / 128, 2);
    for (int l = 0; l < 4; l++) {
        int K = (l == 0) ? 128 : 256;
        int agg_p = (Np + 7) / 8, agg_a = (Na + 7) / 8;
        if (K == 128) {
            aggregate_mean_bf<128><<<agg_p, 256>>>(iaH, iaL, off_pw, col_pw, mwH, mwL, Np);
            aggregate_mean_bf<128><<<agg_p, 256>>>(ipH, ipL, off_pc, col_pc, mcH, mcL, Np);
            aggregate_mean_bf<128><<<agg_a, 256>>>(ipH, ipL, off_a,  col_a,  maH, maL, Na);
        } else {
            aggregate_mean_bf<256><<<agg_p, 256>>>(iaH, iaL, off_pw, col_pw, mwH, mwL, Np);
            aggregate_mean_bf<256><<<agg_p, 256>>>(ipH, ipL, off_pc, col_pc, mcH, mcL, Np);
            aggregate_mean_bf<256><<<agg_a, 256>>>(ipH, ipL, off_a,  col_a,  maH, maL, Na);
        }
        int s = l * 5;
        const float* bias_a;
        if (l == 0) bias_a = bl1 + 256;
        else        bias_a = bl + (size_t)((l - 1) * 3 + 1) * 256;
        int relu = (l < 3) ? 1 : 0;
        int ob = (l % 2 == 0) ? 0 : 1;
        gemm_mma<<<gp, 512>>>(3,
            mwH, mwL, wtH + (size_t)(s + 0) * WSTRIDE, wtL + (size_t)(s + 0) * WSTRIDE,
            mcH, mcL, wtH + (size_t)(s + 1) * WSTRIDE, wtL + (size_t)(s + 1) * WSTRIDE,
            ipH, ipL, wtH + (size_t)(s + 2) * WSTRIDE, wtL + (size_t)(s + 2) * WSTRIDE,
            blp + l * 256, xpH[ob], xpL[ob], Np, K, relu);
        gemm_mma<<<ga, 512>>>(2,
            maH, maL, wtH + (size_t)(s + 3) * WSTRIDE, wtL + (size_t)(s + 3) * WSTRIDE,
            iaH, iaL, wtH + (size_t)(s + 4) * WSTRIDE, wtL + (size_t)(s + 4) * WSTRIDE,
            (const __nv_bfloat16*)nullptr, (const __nv_bfloat16*)nullptr,
            (const __nv_bfloat16*)nullptr, (const __nv_bfloat16*)nullptr,
            bias_a, xaH[ob], xaL[ob], Na, K, relu);
        iaH = xaH[ob]; iaL = xaL[ob];
        ipH = xpH[ob]; ipL = xpL[ob];
    }

    // ---- decoder ----
    init_out<<<(EL + 255) / 256, 256>>>(out, db2, EL);
    decoder_mma<<<dim3((EL + 127) / 128, 2), 512>>>(
        iaH, iaL, esrc, edst,
        wtH + (size_t)20 * WSTRIDE, wtL + (size_t)20 * WSTRIDE,
        wtH + (size_t)21 * WSTRIDE, wtL + (size_t)21 * WSTRIDE,
        db1, dW2, out, EL);
}

// round 5
// speedup vs baseline: 2.0021x; 1.1792x over previous
#include <cuda_runtime.h>
#include <cuda_bf16.h>
#include <cstdint>
#include <cstddef>

#define CDIM 256
#define NA_MAX 50000
#define NP_MAX 100000
#define E_MAX  800000
#define WSTRIDE 65536   // 256*256 slot stride for transposed weights
#define NSLOT 22        // 4 layers * 5 + 2 decoder halves

// ---------------- static scratch (allocation-free rule) ----------------
// fp32 activations (ping-pong) + aggregation outputs
__device__ float g_xa0[NA_MAX * CDIM], g_xa1[NA_MAX * CDIM];
__device__ float g_xp0[NP_MAX * CDIM], g_xp1[NP_MAX * CDIM];
__device__ float g_mw [NP_MAX * CDIM], g_mc [NP_MAX * CDIM], g_ma [NA_MAX * CDIM];
// weights: transposed [256,K], hi/lo bf16 split
__device__ __nv_bfloat16 g_wtH[NSLOT * WSTRIDE], g_wtL[NSLOT * WSTRIDE];
__device__ float g_blp[4 * CDIM];
// CSR
__device__ int g_off_pw[NP_MAX + 1], g_off_pc[NP_MAX + 1], g_off_a[NA_MAX + 1];
__device__ int g_col_pw[E_MAX], g_col_pc[E_MAX], g_col_a[E_MAX];
__device__ int g_cnt[NP_MAX], g_cur[NP_MAX];

// ================= CSR build =================
__global__ void count_kernel(const int* __restrict__ dst, int E, int* __restrict__ cnt) {
    int i = blockIdx.x * blockDim.x + threadIdx.x;
    if (i < E) atomicAdd(&cnt[dst[i]], 1);
}
__global__ void scan_kernel(const int* __restrict__ cnt, int* __restrict__ off, int n) {
    __shared__ int wsum[32];
    __shared__ int sbase;
    int tid = threadIdx.x, lane = tid & 31, wid = tid >> 5;
    if (tid == 0) { off[0] = 0; sbase = 0; }
    __syncthreads();
    for (int start = 0; start < n; start += 1024) {
        int i = start + tid;
        int v = (i < n) ? cnt[i] : 0;
        int x = v;
        #pragma unroll
        for (int o = 1; o < 32; o <<= 1) { int y = __shfl_up_sync(0xffffffffu, x, o); if (lane >= o) x += y; }
        if (lane == 31) wsum[wid] = x;
        __syncthreads();
        if (wid == 0) {
            int w = wsum[lane];
            #pragma unroll
            for (int o = 1; o < 32; o <<= 1) { int y = __shfl_up_sync(0xffffffffu, w, o); if (lane >= o) w += y; }
            wsum[lane] = w;
        }
        __syncthreads();
        int incl = x + (wid > 0 ? wsum[wid - 1] : 0);
        int base = sbase;
        if (i < n) off[i + 1] = base + incl;
        __syncthreads();
        if (tid == 1023) sbase = base + incl;
        __syncthreads();
    }
}
__global__ void fill_kernel(const int* __restrict__ src, const int* __restrict__ dst, int E,
                            int* __restrict__ cur, int* __restrict__ col) {
    int i = blockIdx.x * blockDim.x + threadIdx.x;
    if (i < E) {
        int p = atomicAdd(&cur[dst[i]], 1);
        col[p] = src[i];
    }
}

// ================= conversions =================
static __device__ __forceinline__ void split2(float v, __nv_bfloat16& h, __nv_bfloat16& l) {
    h = __float2bfloat16(v);
    l = __float2bfloat16(v - __bfloat162float(h));
}
// W [K,256] fp32 (+optional add) -> transposed split [256,K] bf16
__global__ void wt_convert(const float* __restrict__ A, const float* __restrict__ B, int K,
                           __nv_bfloat16* __restrict__ oh, __nv_bfloat16* __restrict__ ol) {
    int i = blockIdx.x * blockDim.x + threadIdx.x;
    if (i >= 256 * K) return;
    int k = i % K, n = i / K;
    float v = A[k * 256 + n];
    if (B) v += B[k * 256 + n];
    __nv_bfloat16 h, l; split2(v, h, l);
    oh[i] = h; ol[i] = l;
}
__global__ void bias_comb(const float* __restrict__ a, const float* __restrict__ b, float* __restrict__ o) {
    int i = threadIdx.x;
    o[i] = a[i] + b[i];
}

// ================= mean aggregation (fp32), warp per row, 2-way edge unroll =================
template <int F>
__global__ void aggregate_mean(const float* __restrict__ xsrc,
                               const int* __restrict__ off, const int* __restrict__ col,
                               float* __restrict__ out, int ndst) {
    int warp = (blockIdx.x * blockDim.x + threadIdx.x) >> 5;
    int lane = threadIdx.x & 31;
    if (warp >= ndst) return;
    constexpr int S = F / 128;   // float4 per lane: 1 (F=128) or 2 (F=256)
    float4 acc[S];
    #pragma unroll
    for (int s = 0; s < S; s++) acc[s] = make_float4(0.f, 0.f, 0.f, 0.f);
    int e0 = off[warp], e1 = off[warp + 1];
    int e = e0;
    for (; e + 1 < e1; e += 2) {
        const float4* r0 = (const float4*)(xsrc + (size_t)col[e] * F);
        const float4* r1 = (const float4*)(xsrc + (size_t)col[e + 1] * F);
        float4 v0[S], v1[S];
        #pragma unroll
        for (int s = 0; s < S; s++) { v0[s] = __ldg(&r0[lane + s * 32]); v1[s] = __ldg(&r1[lane + s * 32]); }
        #pragma unroll
        for (int s = 0; s < S; s++) {
            acc[s].x += v0[s].x + v1[s].x; acc[s].y += v0[s].y + v1[s].y;
            acc[s].z += v0[s].z + v1[s].z; acc[s].w += v0[s].w + v1[s].w;
        }
    }
    if (e < e1) {
        const float4* r0 = (const float4*)(xsrc + (size_t)col[e] * F);
        #pragma unroll
        for (int s = 0; s < S; s++) {
            float4 v = __ldg(&r0[lane + s * 32]);
            acc[s].x += v.x; acc[s].y += v.y; acc[s].z += v.z; acc[s].w += v.w;
        }
    }
    float inv = 1.f / fmaxf((float)(e1 - e0), 1.f);
    float4* orow = (float4*)(out + (size_t)warp * F);
    #pragma unroll
    for (int s = 0; s < S; s++) {
        acc[s].x *= inv; acc[s].y *= inv; acc[s].z *= inv; acc[s].w *= inv;
        orow[lane + s * 32] = acc[s];
    }
}

// ================= mma.sync helpers =================
static __device__ __forceinline__ void mma16816(float* c, const uint32_t* a, const uint32_t* b) {
    asm volatile(
        "mma.sync.aligned.m16n8k16.row.col.f32.bf16.bf16.f32 "
        "{%0,%1,%2,%3}, {%4,%5,%6,%7}, {%8,%9}, {%0,%1,%2,%3};"
        : "+f"(c[0]), "+f"(c[1]), "+f"(c[2]), "+f"(c[3])
        : "r"(a[0]), "r"(a[1]), "r"(a[2]), "r"(a[3]), "r"(b[0]), "r"(b[1]));
}
static __device__ __forceinline__ void ldm_x4(uint32_t* r, uint32_t addr) {
    asm volatile("ldmatrix.sync.aligned.m8n8.x4.shared.b16 {%0,%1,%2,%3}, [%4];"
                 : "=r"(r[0]), "=r"(r[1]), "=r"(r[2]), "=r"(r[3]) : "r"(addr));
}

#define SPAD 40  // smem row stride in bf16 (32 + 8 pad)

// pack 8 fp32 -> 8 hi bf16 + 8 lo bf16 (uint4 each)
static __device__ __forceinline__ void split8(const float4& f0, const float4& f1,
                                              uint4& H, uint4& L) {
    __nv_bfloat162 h[4], l[4];
    split2(f0.x, h[0].x, l[0].x); split2(f0.y, h[0].y, l[0].y);
    split2(f0.z, h[1].x, l[1].x); split2(f0.w, h[1].y, l[1].y);
    split2(f1.x, h[2].x, l[2].x); split2(f1.y, h[2].y, l[2].y);
    split2(f1.z, h[3].x, l[3].x); split2(f1.w, h[3].y, l[3].y);
    H = *(uint4*)h; L = *(uint4*)l;
}

// ================= mma.sync GEMM: out = relu?(sum_p A_p@W_p^T + bias) =================
// A_p: [M,K] fp32 row-major (split to bf16 hi/lo on smem fill);
// B_p: [256,K] bf16 hi/lo (pre-transposed weights).
// CTA 128x128, 512 thr (16 warps 4x4), warp tile 32x32, BK=32, 3-pass hi/lo.
__global__ __launch_bounds__(512, 1)
void gemm_mma(int npair,
              const float* __restrict__ A0,
              const __nv_bfloat16* __restrict__ B0h, const __nv_bfloat16* __restrict__ B0l,
              const float* __restrict__ A1,
              const __nv_bfloat16* __restrict__ B1h, const __nv_bfloat16* __restrict__ B1l,
              const float* __restrict__ A2,
              const __nv_bfloat16* __restrict__ B2h, const __nv_bfloat16* __restrict__ B2l,
              const float* __restrict__ bias, float* __restrict__ outp,
              int M, int K, int relu) {
    __shared__ __nv_bfloat16 sAh[128 * SPAD], sAl[128 * SPAD];
    __shared__ __nv_bfloat16 sBh[128 * SPAD], sBl[128 * SPAD];
    int tid = threadIdx.x, lane = tid & 31, warp = tid >> 5;
    int wm = warp >> 2, wn = warp & 3;
    int m0 = blockIdx.x * 128, n0 = blockIdx.y * 128;
    float acc[2][4][4];
    #pragma unroll
    for (int i = 0; i < 2; i++)
        #pragma unroll
        for (int j = 0; j < 4; j++)
            #pragma unroll
            for (int q = 0; q < 4; q++) acc[i][j][q] = 0.f;

    int cpp = K >> 5;
    int total = npair * cpp;
    int lrow = tid >> 2, lkq = (tid & 3) * 8;
    bool aval = (m0 + lrow) < M;

    // ldmatrix per-lane address components
    uint32_t sAh_u = (uint32_t)__cvta_generic_to_shared(sAh);
    uint32_t sAl_u = (uint32_t)__cvta_generic_to_shared(sAl);
    uint32_t sBh_u = (uint32_t)__cvta_generic_to_shared(sBh);
    uint32_t sBl_u = (uint32_t)__cvta_generic_to_shared(sBl);
    int aRow = wm * 32 + (lane & 15);
    int aCol = (lane >> 4) * 8;
    int bRow = wn * 32 + (lane & 7) + ((lane & 16) ? 8 : 0);
    int bCol = ((lane >> 3) & 1) * 8;

    float4 fa0, fa1;
    uint4 vbh, vbl;
    auto fetch = [&](int t) {
        int p = t / cpp, kc = t - p * cpp;
        const float* A = (p == 0) ? A0 : ((p == 1) ? A1 : A2);
        const __nv_bfloat16* Bh = (p == 0) ? B0h : ((p == 1) ? B1h : B2h);
        const __nv_bfloat16* Bl = (p == 0) ? B0l : ((p == 1) ? B1l : B2l);
        size_t ao = (size_t)(m0 + lrow) * K + kc * 32 + lkq;
        size_t bo = (size_t)(n0 + lrow) * K + kc * 32 + lkq;
        if (aval) {
            fa0 = *(const float4*)(A + ao);
            fa1 = *(const float4*)(A + ao + 4);
        } else {
            fa0 = make_float4(0.f, 0.f, 0.f, 0.f);
            fa1 = fa0;
        }
        vbh = *(const uint4*)(Bh + bo);
        vbl = *(const uint4*)(Bl + bo);
    };
    fetch(0);
    for (int t = 0; t < total; t++) {
        int so = lrow * SPAD + lkq;
        uint4 H, L;
        split8(fa0, fa1, H, L);
        *(uint4*)(sAh + so) = H; *(uint4*)(sAl + so) = L;
        *(uint4*)(sBh + so) = vbh; *(uint4*)(sBl + so) = vbl;
        __syncthreads();
        if (t + 1 < total) fetch(t + 1);
        #pragma unroll
        for (int ks = 0; ks < 2; ks++) {
            int k = ks * 16;
            uint32_t ah[2][4], al[2][4], bh[4][2], bl[4][2];
            #pragma unroll
            for (int i = 0; i < 2; i++) {
                uint32_t off = (uint32_t)(((aRow + i * 16) * SPAD + k + aCol) * 2);
                ldm_x4(ah[i], sAh_u + off);
                ldm_x4(al[i], sAl_u + off);
            }
            #pragma unroll
            for (int jj = 0; jj < 2; jj++) {
                uint32_t off = (uint32_t)(((bRow + jj * 16) * SPAD + k + bCol) * 2);
                ldm_x4(&bh[jj * 2][0], sBh_u + off);
                ldm_x4(&bl[jj * 2][0], sBl_u + off);
            }
            #pragma unroll
            for (int i = 0; i < 2; i++)
                #pragma unroll
                for (int j = 0; j < 4; j++) {
                    mma16816(acc[i][j], ah[i], bh[j]);
                    mma16816(acc[i][j], ah[i], bl[j]);
                    mma16816(acc[i][j], al[i], bh[j]);
                }
        }
        __syncthreads();
    }
    // epilogue: bias + relu -> fp32
    #pragma unroll
    for (int i = 0; i < 2; i++) {
        int r0 = m0 + wm * 32 + i * 16 + (lane >> 2);
        #pragma unroll
        for (int j = 0; j < 4; j++) {
            int c = n0 + wn * 32 + j * 8 + (lane & 3) * 2;
            float b0 = __ldg(&bias[c]), b1v = __ldg(&bias[c + 1]);
            if (r0 < M) {
                float v0 = acc[i][j][0] + b0, v1 = acc[i][j][1] + b1v;
                if (relu) { v0 = fmaxf(v0, 0.f); v1 = fmaxf(v1, 0.f); }
                *(float2*)(outp + (size_t)r0 * 256 + c) = make_float2(v0, v1);
            }
            if (r0 + 8 < M) {
                float v0 = acc[i][j][2] + b0, v1 = acc[i][j][3] + b1v;
                if (relu) { v0 = fmaxf(v0, 0.f); v1 = fmaxf(v1, 0.f); }
                *(float2*)(outp + (size_t)(r0 + 8) * 256 + c) = make_float2(v0, v1);
            }
        }
    }
}

// ================= decoder init =================
__global__ void init_out(float* __restrict__ out, const float* __restrict__ b2, int n) {
    int i = blockIdx.x * blockDim.x + threadIdx.x;
    if (i < n) out[i] = b2[0];
}

// ================= fused decoder: gather-A mma GEMM + relu-dot epilogue =================
__global__ __launch_bounds__(512, 1)
void decoder_mma(const float* __restrict__ xa,
                 const int* __restrict__ esrc, const int* __restrict__ edst,
                 const __nv_bfloat16* __restrict__ B0h, const __nv_bfloat16* __restrict__ B0l,
                 const __nv_bfloat16* __restrict__ B1h, const __nv_bfloat16* __restrict__ B1l,
                 const float* __restrict__ b1, const float* __restrict__ W2,
                 float* __restrict__ out, int M) {
    __shared__ __nv_bfloat16 sAh[128 * SPAD], sAl[128 * SPAD];
    __shared__ __nv_bfloat16 sBh[128 * SPAD], sBl[128 * SPAD];
    __shared__ float red[128];
    int tid = threadIdx.x, lane = tid & 31, warp = tid >> 5;
    int wm = warp >> 2, wn = warp & 3;
    int m0 = blockIdx.x * 128, n0 = blockIdx.y * 128;
    float acc[2][4][4];
    #pragma unroll
    for (int i = 0; i < 2; i++)
        #pragma unroll
        for (int j = 0; j < 4; j++)
            #pragma unroll
            for (int q = 0; q < 4; q++) acc[i][j][q] = 0.f;

    int lrow = tid >> 2, lkq = (tid & 3) * 8;
    bool aval = (m0 + lrow) < M;
    int a0i = aval ? __ldg(&esrc[m0 + lrow]) : 0;
    int a1i = aval ? __ldg(&edst[m0 + lrow]) : 0;
    if (tid < 128) red[tid] = 0.f;

    uint32_t sAh_u = (uint32_t)__cvta_generic_to_shared(sAh);
    uint32_t sAl_u = (uint32_t)__cvta_generic_to_shared(sAl);
    uint32_t sBh_u = (uint32_t)__cvta_generic_to_shared(sBh);
    uint32_t sBl_u = (uint32_t)__cvta_generic_to_shared(sBl);
    int aRow = wm * 32 + (lane & 15);
    int aCol = (lane >> 4) * 8;
    int bRow = wn * 32 + (lane & 7) + ((lane & 16) ? 8 : 0);
    int bCol = ((lane >> 3) & 1) * 8;

    float4 fa0, fa1;
    uint4 vbh, vbl;
    auto fetch = [&](int t) {
        int p = t >> 3, kc = t & 7;
        const __nv_bfloat16* Bh = p ? B1h : B0h;
        const __nv_bfloat16* Bl = p ? B1l : B0l;
        int ar = p ? a1i : a0i;
        size_t ao = (size_t)ar * 256 + kc * 32 + lkq;
        size_t bo = (size_t)(n0 + lrow) * 256 + kc * 32 + lkq;
        if (aval) {
            fa0 = *(const float4*)(xa + ao);
            fa1 = *(const float4*)(xa + ao + 4);
        } else {
            fa0 = make_float4(0.f, 0.f, 0.f, 0.f);
            fa1 = fa0;
        }
        vbh = *(const uint4*)(Bh + bo);
        vbl = *(const uint4*)(Bl + bo);
    };
    fetch(0);
    for (int t = 0; t < 16; t++) {
        int so = lrow * SPAD + lkq;
        uint4 H, L;
        split8(fa0, fa1, H, L);
        *(uint4*)(sAh + so) = H; *(uint4*)(sAl + so) = L;
        *(uint4*)(sBh + so) = vbh; *(uint4*)(sBl + so) = vbl;
        __syncthreads();
        if (t + 1 < 16) fetch(t + 1);
        #pragma unroll
        for (int ks = 0; ks < 2; ks++) {
            int k = ks * 16;
            uint32_t ah[2][4], al[2][4], bh[4][2], bl[4][2];
            #pragma unroll
            for (int i = 0; i < 2; i++) {
                uint32_t off = (uint32_t)(((aRow + i * 16) * SPAD + k + aCol) * 2);
                ldm_x4(ah[i], sAh_u + off);
                ldm_x4(al[i], sAl_u + off);
            }
            #pragma unroll
            for (int jj = 0; jj < 2; jj++) {
                uint32_t off = (uint32_t)(((bRow + jj * 16) * SPAD + k + bCol) * 2);
                ldm_x4(&bh[jj * 2][0], sBh_u + off);
                ldm_x4(&bl[jj * 2][0], sBl_u + off);
            }
            #pragma unroll
            for (int i = 0; i < 2; i++)
                #pragma unroll
                for (int j = 0; j < 4; j++) {
                    mma16816(acc[i][j], ah[i], bh[j]);
                    mma16816(acc[i][j], ah[i], bl[j]);
                    mma16816(acc[i][j], al[i], bh[j]);
                }
        }
        __syncthreads();
    }
    // epilogue: relu(acc + b1) dot W2, reduce per row
    #pragma unroll
    for (int i = 0; i < 2; i++) {
        int rl = wm * 32 + i * 16 + (lane >> 2);
        float p0 = 0.f, p1 = 0.f;
        #pragma unroll
        for (int j = 0; j < 4; j++) {
            int c = n0 + wn * 32 + j * 8 + (lane & 3) * 2;
            float b0 = __ldg(&b1[c]), b1v = __ldg(&b1[c + 1]);
            float w0 = __ldg(&W2[c]), w1 = __ldg(&W2[c + 1]);
            p0 += fmaxf(acc[i][j][0] + b0, 0.f) * w0 + fmaxf(acc[i][j][1] + b1v, 0.f) * w1;
            p1 += fmaxf(acc[i][j][2] + b0, 0.f) * w0 + fmaxf(acc[i][j][3] + b1v, 0.f) * w1;
        }
        atomicAdd(&red[rl], p0);
        atomicAdd(&red[rl + 8], p1);
    }
    __syncthreads();
    if (tid < 128 && m0 + tid < M) atomicAdd(&out[m0 + tid], red[tid]);
}

// ================= launcher =================
extern "C" void kernel_launch(void* const* d_in, const int* in_sizes, int n_in,
                              void* d_out, int out_size) {
    const float* x_author = (const float*)d_in[0];
    const float* x_paper  = (const float*)d_in[1];
    const float* Wl1 = (const float*)d_in[2];
    const float* bl1 = (const float*)d_in[3];
    const float* Wr1 = (const float*)d_in[4];
    const float* Wl  = (const float*)d_in[5];
    const float* bl  = (const float*)d_in[6];
    const float* Wr  = (const float*)d_in[7];
    const float* dW1 = (const float*)d_in[8];
    const float* db1 = (const float*)d_in[9];
    const float* dW2 = (const float*)d_in[10];
    const float* db2 = (const float*)d_in[11];
    const int* wsrc = (const int*)d_in[12];
    const int* wdst = (const int*)d_in[13];
    const int* csrc = (const int*)d_in[14];
    const int* cdst = (const int*)d_in[15];
    const int* esrc = (const int*)d_in[16];
    const int* edst = (const int*)d_in[17];
    float* out = (float*)d_out;

    int Na = in_sizes[0] / 128;
    int Np = in_sizes[1] / 128;
    int E  = in_sizes[12];
    int EL = in_sizes[16];

    float *xa0, *xa1, *xp0, *xp1, *mw, *mc, *ma, *blp;
    __nv_bfloat16 *wtH, *wtL;
    int *off_pw, *off_pc, *off_a, *col_pw, *col_pc, *col_a, *cnt, *cur;
    cudaGetSymbolAddress((void**)&xa0, g_xa0); cudaGetSymbolAddress((void**)&xa1, g_xa1);
    cudaGetSymbolAddress((void**)&xp0, g_xp0); cudaGetSymbolAddress((void**)&xp1, g_xp1);
    cudaGetSymbolAddress((void**)&mw, g_mw); cudaGetSymbolAddress((void**)&mc, g_mc);
    cudaGetSymbolAddress((void**)&ma, g_ma);
    cudaGetSymbolAddress((void**)&wtH, g_wtH); cudaGetSymbolAddress((void**)&wtL, g_wtL);
    cudaGetSymbolAddress((void**)&blp, g_blp);
    cudaGetSymbolAddress((void**)&off_pw, g_off_pw); cudaGetSymbolAddress((void**)&off_pc, g_off_pc);
    cudaGetSymbolAddress((void**)&off_a, g_off_a);
    cudaGetSymbolAddress((void**)&col_pw, g_col_pw); cudaGetSymbolAddress((void**)&col_pc, g_col_pc);
    cudaGetSymbolAddress((void**)&col_a, g_col_a);
    cudaGetSymbolAddress((void**)&cnt, g_cnt); cudaGetSymbolAddress((void**)&cur, g_cur);

    int egrid = (E + 255) / 256;

    // ---- CSR build ----
    cudaMemsetAsync(cnt, 0, Np * sizeof(int));
    count_kernel<<<egrid, 256>>>(wdst, E, cnt);
    scan_kernel<<<1, 1024>>>(cnt, off_pw, Np);
    cudaMemcpyAsync(cur, off_pw, Np * sizeof(int), cudaMemcpyDeviceToDevice);
    fill_kernel<<<egrid, 256>>>(wsrc, wdst, E, cur, col_pw);

    cudaMemsetAsync(cnt, 0, Np * sizeof(int));
    count_kernel<<<egrid, 256>>>(cdst, E, cnt);
    scan_kernel<<<1, 1024>>>(cnt, off_pc, Np);
    cudaMemcpyAsync(cur, off_pc, Np * sizeof(int), cudaMemcpyDeviceToDevice);
    fill_kernel<<<egrid, 256>>>(csrc, cdst, E, cur, col_pc);

    cudaMemsetAsync(cnt, 0, Na * sizeof(int));
    count_kernel<<<egrid, 256>>>(wsrc, E, cnt);
    scan_kernel<<<1, 1024>>>(cnt, off_a, Na);
    cudaMemcpyAsync(cur, off_a, Na * sizeof(int), cudaMemcpyDeviceToDevice);
    fill_kernel<<<egrid, 256>>>(wdst, wsrc, E, cur, col_a);

    // ---- weight transpose + split (slots: l*5 + {Wl0,Wl2,Wr0+Wr2,Wl1,Wr1}; 20,21 = dec) ----
    for (int l = 0; l < 4; l++) {
        int K = (l == 0) ? 128 : 256;
        const float *wl0, *wl1e, *wl2, *wr0, *wr1e, *wr2, *b0, *b2e;
        if (l == 0) {
            wl0 = Wl1; wl1e = Wl1 + 128 * 256; wl2 = Wl1 + 2 * 128 * 256;
            wr0 = Wr1; wr1e = Wr1 + 128 * 256; wr2 = Wr1 + 2 * 128 * 256;
            b0 = bl1; b2e = bl1 + 512;
        } else {
            int li = l - 1;
            wl0  = Wl + (size_t)(li * 3 + 0) * 65536;
            wl1e = Wl + (size_t)(li * 3 + 1) * 65536;
            wl2  = Wl + (size_t)(li * 3 + 2) * 65536;
            wr0  = Wr + (size_t)(li * 3 + 0) * 65536;
            wr1e = Wr + (size_t)(li * 3 + 1) * 65536;
            wr2  = Wr + (size_t)(li * 3 + 2) * 65536;
            b0   = bl + (size_t)(li * 3 + 0) * 256;
            b2e  = bl + (size_t)(li * 3 + 2) * 256;
        }
        int g = (256 * K + 255) / 256;
        int s = l * 5;
        wt_convert<<<g, 256>>>(wl0, (const float*)nullptr, K, wtH + (size_t)(s + 0) * WSTRIDE, wtL + (size_t)(s + 0) * WSTRIDE);
        wt_convert<<<g, 256>>>(wl2, (const float*)nullptr, K, wtH + (size_t)(s + 1) * WSTRIDE, wtL + (size_t)(s + 1) * WSTRIDE);
        wt_convert<<<g, 256>>>(wr0, wr2,                  K, wtH + (size_t)(s + 2) * WSTRIDE, wtL + (size_t)(s + 2) * WSTRIDE);
        wt_convert<<<g, 256>>>(wl1e, (const float*)nullptr, K, wtH + (size_t)(s + 3) * WSTRIDE, wtL + (size_t)(s + 3) * WSTRIDE);
        wt_convert<<<g, 256>>>(wr1e, (const float*)nullptr, K, wtH + (size_t)(s + 4) * WSTRIDE, wtL + (size_t)(s + 4) * WSTRIDE);
        bias_comb<<<1, 256>>>(b0, b2e, blp + l * 256);
    }
    wt_convert<<<256, 256>>>(dW1,             (const float*)nullptr, 256, wtH + (size_t)20 * WSTRIDE, wtL + (size_t)20 * WSTRIDE);
    wt_convert<<<256, 256>>>(dW1 + 256 * 256, (const float*)nullptr, 256, wtH + (size_t)21 * WSTRIDE, wtL + (size_t)21 * WSTRIDE);

    // ---- layers ----
    const float *ia = x_author, *ip = x_paper;
    float* outs_a[4] = { xa0, xa1, xa0, xa1 };
    float* outs_p[4] = { xp0, xp1, xp0, xp1 };
    dim3 gp((Np + 127) / 128, 2), ga((Na + 127) / 128, 2);
    for (int l = 0; l < 4; l++) {
        int K = (l == 0) ? 128 : 256;
        int agg_p = (Np + 7) / 8, agg_a = (Na + 7) / 8;
        if (K == 128) {
            aggregate_mean<128><<<agg_p, 256>>>(ia, off_pw, col_pw, mw, Np);
            aggregate_mean<128><<<agg_p, 256>>>(ip, off_pc, col_pc, mc, Np);
            aggregate_mean<128><<<agg_a, 256>>>(ip, off_a,  col_a,  ma, Na);
        } else {
            aggregate_mean<256><<<agg_p, 256>>>(ia, off_pw, col_pw, mw, Np);
            aggregate_mean<256><<<agg_p, 256>>>(ip, off_pc, col_pc, mc, Np);
            aggregate_mean<256><<<agg_a, 256>>>(ip, off_a,  col_a,  ma, Na);
        }
        int s = l * 5;
        const float* bias_a;
        if (l == 0) bias_a = bl1 + 256;
        else        bias_a = bl + (size_t)((l - 1) * 3 + 1) * 256;
        int relu = (l < 3) ? 1 : 0;
        gemm_mma<<<gp, 512>>>(3,
            mw, wtH + (size_t)(s + 0) * WSTRIDE, wtL + (size_t)(s + 0) * WSTRIDE,
            mc, wtH + (size_t)(s + 1) * WSTRIDE, wtL + (size_t)(s + 1) * WSTRIDE,
            ip, wtH + (size_t)(s + 2) * WSTRIDE, wtL + (size_t)(s + 2) * WSTRIDE,
            blp + l * 256, outs_p[l], Np, K, relu);
        gemm_mma<<<ga, 512>>>(2,
            ma, wtH + (size_t)(s + 3) * WSTRIDE, wtL + (size_t)(s + 3) * WSTRIDE,
            ia, wtH + (size_t)(s + 4) * WSTRIDE, wtL + (size_t)(s + 4) * WSTRIDE,
            (const float*)nullptr, (const __nv_bfloat16*)nullptr, (const __nv_bfloat16*)nullptr,
            bias_a, outs_a[l], Na, K, relu);
        ia = outs_a[l];
        ip = outs_p[l];
    }

    // ---- decoder ----
    init_out<<<(EL + 255) / 256, 256>>>(out, db2, EL);
    decoder_mma<<<dim3((EL + 127) / 128, 2), 512>>>(
        ia, esrc, edst,
        wtH + (size_t)20 * WSTRIDE, wtL + (size_t)20 * WSTRIDE,
        wtH + (size_t)21 * WSTRIDE, wtL + (size_t)21 * WSTRIDE,
        db1, dW2, out, EL);
}

// round 6
// speedup vs baseline: 2.0104x; 1.0041x over previous
#include <cuda_runtime.h>
#include <cuda_bf16.h>
#include <cstdint>
#include <cstddef>

#define CDIM 256
#define NA_MAX 50000
#define NP_MAX 100000
#define E_MAX  800000
#define WSTRIDE 65536   // 256*256 slot stride for transposed weights
#define NSLOT 22        // 4 layers * 5 + 2 decoder halves

// ---------------- static scratch (allocation-free rule) ----------------
// fp32 activations (ping-pong) + aggregation outputs
__device__ float g_xa0[NA_MAX * CDIM], g_xa1[NA_MAX * CDIM];
__device__ float g_xp0[NP_MAX * CDIM], g_xp1[NP_MAX * CDIM];
__device__ float g_mw [NP_MAX * CDIM], g_mc [NP_MAX * CDIM], g_ma [NA_MAX * CDIM];
// weights: transposed [256,K], hi/lo bf16 split
__device__ __nv_bfloat16 g_wtH[NSLOT * WSTRIDE], g_wtL[NSLOT * WSTRIDE];
__device__ float g_blp[4 * CDIM];
// CSR
__device__ int g_off_pw[NP_MAX + 1], g_off_pc[NP_MAX + 1], g_off_a[NA_MAX + 1];
__device__ int g_col_pw[E_MAX], g_col_pc[E_MAX], g_col_a[E_MAX];
__device__ int g_cnt[NP_MAX], g_cur[NP_MAX];

// ================= CSR build =================
__global__ void count_kernel(const int* __restrict__ dst, int E, int* __restrict__ cnt) {
    int i = blockIdx.x * blockDim.x + threadIdx.x;
    if (i < E) atomicAdd(&cnt[dst[i]], 1);
}
__global__ void scan_kernel(const int* __restrict__ cnt, int* __restrict__ off, int n) {
    __shared__ int wsum[32];
    __shared__ int sbase;
    int tid = threadIdx.x, lane = tid & 31, wid = tid >> 5;
    if (tid == 0) { off[0] = 0; sbase = 0; }
    __syncthreads();
    for (int start = 0; start < n; start += 1024) {
        int i = start + tid;
        int v = (i < n) ? cnt[i] : 0;
        int x = v;
        #pragma unroll
        for (int o = 1; o < 32; o <<= 1) { int y = __shfl_up_sync(0xffffffffu, x, o); if (lane >= o) x += y; }
        if (lane == 31) wsum[wid] = x;
        __syncthreads();
        if (wid == 0) {
            int w = wsum[lane];
            #pragma unroll
            for (int o = 1; o < 32; o <<= 1) { int y = __shfl_up_sync(0xffffffffu, w, o); if (lane >= o) w += y; }
            wsum[lane] = w;
        }
        __syncthreads();
        int incl = x + (wid > 0 ? wsum[wid - 1] : 0);
        int base = sbase;
        if (i < n) off[i + 1] = base + incl;
        __syncthreads();
        if (tid == 1023) sbase = base + incl;
        __syncthreads();
    }
}
__global__ void fill_kernel(const int* __restrict__ src, const int* __restrict__ dst, int E,
                            int* __restrict__ cur, int* __restrict__ col) {
    int i = blockIdx.x * blockDim.x + threadIdx.x;
    if (i < E) {
        int p = atomicAdd(&cur[dst[i]], 1);
        col[p] = src[i];
    }
}

// ================= conversions =================
static __device__ __forceinline__ void split2(float v, __nv_bfloat16& h, __nv_bfloat16& l) {
    h = __float2bfloat16(v);
    l = __float2bfloat16(v - __bfloat162float(h));
}
// W [K,256] fp32 (+optional add) -> transposed split [256,K] bf16
__global__ void wt_convert(const float* __restrict__ A, const float* __restrict__ B, int K,
                           __nv_bfloat16* __restrict__ oh, __nv_bfloat16* __restrict__ ol) {
    int i = blockIdx.x * blockDim.x + threadIdx.x;
    if (i >= 256 * K) return;
    int k = i % K, n = i / K;
    float v = A[k * 256 + n];
    if (B) v += B[k * 256 + n];
    __nv_bfloat16 h, l; split2(v, h, l);
    oh[i] = h; ol[i] = l;
}
__global__ void bias_comb(const float* __restrict__ a, const float* __restrict__ b, float* __restrict__ o) {
    int i = threadIdx.x;
    o[i] = a[i] + b[i];
}

// ================= mean aggregation (fp32), warp per row, 2-way edge unroll =================
template <int F>
__global__ void aggregate_mean(const float* __restrict__ xsrc,
                               const int* __restrict__ off, const int* __restrict__ col,
                               float* __restrict__ out, int ndst) {
    int warp = (blockIdx.x * blockDim.x + threadIdx.x) >> 5;
    int lane = threadIdx.x & 31;
    if (warp >= ndst) return;
    constexpr int S = F / 128;   // float4 per lane: 1 (F=128) or 2 (F=256)
    float4 acc[S];
    #pragma unroll
    for (int s = 0; s < S; s++) acc[s] = make_float4(0.f, 0.f, 0.f, 0.f);
    int e0 = off[warp], e1 = off[warp + 1];
    int e = e0;
    for (; e + 1 < e1; e += 2) {
        const float4* r0 = (const float4*)(xsrc + (size_t)col[e] * F);
        const float4* r1 = (const float4*)(xsrc + (size_t)col[e + 1] * F);
        float4 v0[S], v1[S];
        #pragma unroll
        for (int s = 0; s < S; s++) { v0[s] = __ldg(&r0[lane + s * 32]); v1[s] = __ldg(&r1[lane + s * 32]); }
        #pragma unroll
        for (int s = 0; s < S; s++) {
            acc[s].x += v0[s].x + v1[s].x; acc[s].y += v0[s].y + v1[s].y;
            acc[s].z += v0[s].z + v1[s].z; acc[s].w += v0[s].w + v1[s].w;
        }
    }
    if (e < e1) {
        const float4* r0 = (const float4*)(xsrc + (size_t)col[e] * F);
        #pragma unroll
        for (int s = 0; s < S; s++) {
            float4 v = __ldg(&r0[lane + s * 32]);
            acc[s].x += v.x; acc[s].y += v.y; acc[s].z += v.z; acc[s].w += v.w;
        }
    }
    float inv = 1.f / fmaxf((float)(e1 - e0), 1.f);
    float4* orow = (float4*)(out + (size_t)warp * F);
    #pragma unroll
    for (int s = 0; s < S; s++) {
        acc[s].x *= inv; acc[s].y *= inv; acc[s].z *= inv; acc[s].w *= inv;
        orow[lane + s * 32] = acc[s];
    }
}

// ================= mma.sync helpers =================
static __device__ __forceinline__ void mma16816(float* c, const uint32_t* a, const uint32_t* b) {
    asm volatile(
        "mma.sync.aligned.m16n8k16.row.col.f32.bf16.bf16.f32 "
        "{%0,%1,%2,%3}, {%4,%5,%6,%7}, {%8,%9}, {%0,%1,%2,%3};"
        : "+f"(c[0]), "+f"(c[1]), "+f"(c[2]), "+f"(c[3])
        : "r"(a[0]), "r"(a[1]), "r"(a[2]), "r"(a[3]), "r"(b[0]), "r"(b[1]));
}
static __device__ __forceinline__ void ldm_x4(uint32_t* r, uint32_t addr) {
    asm volatile("ldmatrix.sync.aligned.m8n8.x4.shared.b16 {%0,%1,%2,%3}, [%4];"
                 : "=r"(r[0]), "=r"(r[1]), "=r"(r[2]), "=r"(r[3]) : "r"(addr));
}

#define SPAD 40  // smem row stride in bf16 (32 + 8 pad)

// pack 8 fp32 -> 8 hi bf16 + 8 lo bf16 (uint4 each)
static __device__ __forceinline__ void split8(const float4& f0, const float4& f1,
                                              uint4& H, uint4& L) {
    __nv_bfloat162 h[4], l[4];
    split2(f0.x, h[0].x, l[0].x); split2(f0.y, h[0].y, l[0].y);
    split2(f0.z, h[1].x, l[1].x); split2(f0.w, h[1].y, l[1].y);
    split2(f1.x, h[2].x, l[2].x); split2(f1.y, h[2].y, l[2].y);
    split2(f1.z, h[3].x, l[3].x); split2(f1.w, h[3].y, l[3].y);
    H = *(uint4*)h; L = *(uint4*)l;
}

// ================= mma.sync GEMM: out = relu?(sum_p A_p@W_p^T + bias) =================
// A_p: [M,K] fp32 row-major (split to bf16 hi/lo on smem fill);
// B_p: [256,K] bf16 hi/lo (pre-transposed weights).
// CTA 128x128, 512 thr (16 warps 4x4), warp tile 32x32, BK=32, 3-pass hi/lo.
__global__ __launch_bounds__(512, 1)
void gemm_mma(int npair,
              const float* __restrict__ A0,
              const __nv_bfloat16* __restrict__ B0h, const __nv_bfloat16* __restrict__ B0l,
              const float* __restrict__ A1,
              const __nv_bfloat16* __restrict__ B1h, const __nv_bfloat16* __restrict__ B1l,
              const float* __restrict__ A2,
              const __nv_bfloat16* __restrict__ B2h, const __nv_bfloat16* __restrict__ B2l,
              const float* __restrict__ bias, float* __restrict__ outp,
              int M, int K, int relu) {
    __shared__ __nv_bfloat16 sAh[128 * SPAD], sAl[128 * SPAD];
    __shared__ __nv_bfloat16 sBh[128 * SPAD], sBl[128 * SPAD];
    int tid = threadIdx.x, lane = tid & 31, warp = tid >> 5;
    int wm = warp >> 2, wn = warp & 3;
    int m0 = blockIdx.x * 128, n0 = blockIdx.y * 128;
    float acc[2][4][4];
    #pragma unroll
    for (int i = 0; i < 2; i++)
        #pragma unroll
        for (int j = 0; j < 4; j++)
            #pragma unroll
            for (int q = 0; q < 4; q++) acc[i][j][q] = 0.f;

    int cpp = K >> 5;
    int total = npair * cpp;
    int lrow = tid >> 2, lkq = (tid & 3) * 8;
    bool aval = (m0 + lrow) < M;

    // ldmatrix per-lane address components
    uint32_t sAh_u = (uint32_t)__cvta_generic_to_shared(sAh);
    uint32_t sAl_u = (uint32_t)__cvta_generic_to_shared(sAl);
    uint32_t sBh_u = (uint32_t)__cvta_generic_to_shared(sBh);
    uint32_t sBl_u = (uint32_t)__cvta_generic_to_shared(sBl);
    int aRow = wm * 32 + (lane & 15);
    int aCol = (lane >> 4) * 8;
    int bRow = wn * 32 + (lane & 7) + ((lane & 16) ? 8 : 0);
    int bCol = ((lane >> 3) & 1) * 8;

    float4 fa0, fa1;
    uint4 vbh, vbl;
    auto fetch = [&](int t) {
        int p = t / cpp, kc = t - p * cpp;
        const float* A = (p == 0) ? A0 : ((p == 1) ? A1 : A2);
        const __nv_bfloat16* Bh = (p == 0) ? B0h : ((p == 1) ? B1h : B2h);
        const __nv_bfloat16* Bl = (p == 0) ? B0l : ((p == 1) ? B1l : B2l);
        size_t ao = (size_t)(m0 + lrow) * K + kc * 32 + lkq;
        size_t bo = (size_t)(n0 + lrow) * K + kc * 32 + lkq;
        if (aval) {
            fa0 = *(const float4*)(A + ao);
            fa1 = *(const float4*)(A + ao + 4);
        } else {
            fa0 = make_float4(0.f, 0.f, 0.f, 0.f);
            fa1 = fa0;
        }
        vbh = *(const uint4*)(Bh + bo);
        vbl = *(const uint4*)(Bl + bo);
    };
    fetch(0);
    for (int t = 0; t < total; t++) {
        int so = lrow * SPAD + lkq;
        uint4 H, L;
        split8(fa0, fa1, H, L);
        *(uint4*)(sAh + so) = H; *(uint4*)(sAl + so) = L;
        *(uint4*)(sBh + so) = vbh; *(uint4*)(sBl + so) = vbl;
        __syncthreads();
        if (t + 1 < total) fetch(t + 1);
        #pragma unroll
        for (int ks = 0; ks < 2; ks++) {
            int k = ks * 16;
            uint32_t ah[2][4], al[2][4], bh[4][2], bl[4][2];
            #pragma unroll
            for (int i = 0; i < 2; i++) {
                uint32_t off = (uint32_t)(((aRow + i * 16) * SPAD + k + aCol) * 2);
                ldm_x4(ah[i], sAh_u + off);
                ldm_x4(al[i], sAl_u + off);
            }
            #pragma unroll
            for (int jj = 0; jj < 2; jj++) {
                uint32_t off = (uint32_t)(((bRow + jj * 16) * SPAD + k + bCol) * 2);
                ldm_x4(&bh[jj * 2][0], sBh_u + off);
                ldm_x4(&bl[jj * 2][0], sBl_u + off);
            }
            #pragma unroll
            for (int i = 0; i < 2; i++)
                #pragma unroll
                for (int j = 0; j < 4; j++) {
                    mma16816(acc[i][j], ah[i], bh[j]);
                    mma16816(acc[i][j], ah[i], bl[j]);
                    mma16816(acc[i][j], al[i], bh[j]);
                }
        }
        __syncthreads();
    }
    // epilogue: bias + relu -> fp32
    #pragma unroll
    for (int i = 0; i < 2; i++) {
        int r0 = m0 + wm * 32 + i * 16 + (lane >> 2);
        #pragma unroll
        for (int j = 0; j < 4; j++) {
            int c = n0 + wn * 32 + j * 8 + (lane & 3) * 2;
            float b0 = __ldg(&bias[c]), b1v = __ldg(&bias[c + 1]);
            if (r0 < M) {
                float v0 = acc[i][j][0] + b0, v1 = acc[i][j][1] + b1v;
                if (relu) { v0 = fmaxf(v0, 0.f); v1 = fmaxf(v1, 0.f); }
                *(float2*)(outp + (size_t)r0 * 256 + c) = make_float2(v0, v1);
            }
            if (r0 + 8 < M) {
                float v0 = acc[i][j][2] + b0, v1 = acc[i][j][3] + b1v;
                if (relu) { v0 = fmaxf(v0, 0.f); v1 = fmaxf(v1, 0.f); }
                *(float2*)(outp + (size_t)(r0 + 8) * 256 + c) = make_float2(v0, v1);
            }
        }
    }
}

// ================= decoder init =================
__global__ void init_out(float* __restrict__ out, const float* __restrict__ b2, int n) {
    int i = blockIdx.x * blockDim.x + threadIdx.x;
    if (i < n) out[i] = b2[0];
}

// ================= fused decoder: gather-A mma GEMM + relu-dot epilogue =================
__global__ __launch_bounds__(512, 1)
void decoder_mma(const float* __restrict__ xa,
                 const int* __restrict__ esrc, const int* __restrict__ edst,
                 const __nv_bfloat16* __restrict__ B0h, const __nv_bfloat16* __restrict__ B0l,
                 const __nv_bfloat16* __restrict__ B1h, const __nv_bfloat16* __restrict__ B1l,
                 const float* __restrict__ b1, const float* __restrict__ W2,
                 float* __restrict__ out, int M) {
    __shared__ __nv_bfloat16 sAh[128 * SPAD], sAl[128 * SPAD];
    __shared__ __nv_bfloat16 sBh[128 * SPAD], sBl[128 * SPAD];
    __shared__ float red[128];
    int tid = threadIdx.x, lane = tid & 31, warp = tid >> 5;
    int wm = warp >> 2, wn = warp & 3;
    int m0 = blockIdx.x * 128, n0 = blockIdx.y * 128;
    float acc[2][4][4];
    #pragma unroll
    for (int i = 0; i < 2; i++)
        #pragma unroll
        for (int j = 0; j < 4; j++)
            #pragma unroll
            for (int q = 0; q < 4; q++) acc[i][j][q] = 0.f;

    int lrow = tid >> 2, lkq = (tid & 3) * 8;
    bool aval = (m0 + lrow) < M;
    int a0i = aval ? __ldg(&esrc[m0 + lrow]) : 0;
    int a1i = aval ? __ldg(&edst[m0 + lrow]) : 0;
    if (tid < 128) red[tid] = 0.f;

    uint32_t sAh_u = (uint32_t)__cvta_generic_to_shared(sAh);
    uint32_t sAl_u = (uint32_t)__cvta_generic_to_shared(sAl);
    uint32_t sBh_u = (uint32_t)__cvta_generic_to_shared(sBh);
    uint32_t sBl_u = (uint32_t)__cvta_generic_to_shared(sBl);
    int aRow = wm * 32 + (lane & 15);
    int aCol = (lane >> 4) * 8;
    int bRow = wn * 32 + (lane & 7) + ((lane & 16) ? 8 : 0);
    int bCol = ((lane >> 3) & 1) * 8;

    float4 fa0, fa1;
    uint4 vbh, vbl;
    auto fetch = [&](int t) {
        int p = t >> 3, kc = t & 7;
        const __nv_bfloat16* Bh = p ? B1h : B0h;
        const __nv_bfloat16* Bl = p ? B1l : B0l;
        int ar = p ? a1i : a0i;
        size_t ao = (size_t)ar * 256 + kc * 32 + lkq;
        size_t bo = (size_t)(n0 + lrow) * 256 + kc * 32 + lkq;
        if (aval) {
            fa0 = *(const float4*)(xa + ao);
            fa1 = *(const float4*)(xa + ao + 4);
        } else {
            fa0 = make_float4(0.f, 0.f, 0.f, 0.f);
            fa1 = fa0;
        }
        vbh = *(const uint4*)(Bh + bo);
        vbl = *(const uint4*)(Bl + bo);
    };
    fetch(0);
    for (int t = 0; t < 16; t++) {
        int so = lrow * SPAD + lkq;
        uint4 H, L;
        split8(fa0, fa1, H, L);
        *(uint4*)(sAh + so) = H; *(uint4*)(sAl + so) = L;
        *(uint4*)(sBh + so) = vbh; *(uint4*)(sBl + so) = vbl;
        __syncthreads();
        if (t + 1 < 16) fetch(t + 1);
        #pragma unroll
        for (int ks = 0; ks < 2; ks++) {
            int k = ks * 16;
            uint32_t ah[2][4], al[2][4], bh[4][2], bl[4][2];
            #pragma unroll
            for (int i = 0; i < 2; i++) {
                uint32_t off = (uint32_t)(((aRow + i * 16) * SPAD + k + aCol) * 2);
                ldm_x4(ah[i], sAh_u + off);
                ldm_x4(al[i], sAl_u + off);
            }
            #pragma unroll
            for (int jj = 0; jj < 2; jj++) {
                uint32_t off = (uint32_t)(((bRow + jj * 16) * SPAD + k + bCol) * 2);
                ldm_x4(&bh[jj * 2][0], sBh_u + off);
                ldm_x4(&bl[jj * 2][0], sBl_u + off);
            }
            #pragma unroll
            for (int i = 0; i < 2; i++)
                #pragma unroll
                for (int j = 0; j < 4; j++) {
                    mma16816(acc[i][j], ah[i], bh[j]);
                    mma16816(acc[i][j], ah[i], bl[j]);
                    mma16816(acc[i][j], al[i], bh[j]);
                }
        }
        __syncthreads();
    }
    // epilogue: relu(acc + b1) dot W2, reduce per row
    #pragma unroll
    for (int i = 0; i < 2; i++) {
        int rl = wm * 32 + i * 16 + (lane >> 2);
        float p0 = 0.f, p1 = 0.f;
        #pragma unroll
        for (int j = 0; j < 4; j++) {
            int c = n0 + wn * 32 + j * 8 + (lane & 3) * 2;
            float b0 = __ldg(&b1[c]), b1v = __ldg(&b1[c + 1]);
            float w0 = __ldg(&W2[c]), w1 = __ldg(&W2[c + 1]);
            p0 += fmaxf(acc[i][j][0] + b0, 0.f) * w0 + fmaxf(acc[i][j][1] + b1v, 0.f) * w1;
            p1 += fmaxf(acc[i][j][2] + b0, 0.f) * w0 + fmaxf(acc[i][j][3] + b1v, 0.f) * w1;
        }
        atomicAdd(&red[rl], p0);
        atomicAdd(&red[rl + 8], p1);
    }
    __syncthreads();
    if (tid < 128 && m0 + tid < M) atomicAdd(&out[m0 + tid], red[tid]);
}

// ================= launcher =================
extern "C" void kernel_launch(void* const* d_in, const int* in_sizes, int n_in,
                              void* d_out, int out_size) {
    const float* x_author = (const float*)d_in[0];
    const float* x_paper  = (const float*)d_in[1];
    const float* Wl1 = (const float*)d_in[2];
    const float* bl1 = (const float*)d_in[3];
    const float* Wr1 = (const float*)d_in[4];
    const float* Wl  = (const float*)d_in[5];
    const float* bl  = (const float*)d_in[6];
    const float* Wr  = (const float*)d_in[7];
    const float* dW1 = (const float*)d_in[8];
    const float* db1 = (const float*)d_in[9];
    const float* dW2 = (const float*)d_in[10];
    const float* db2 = (const float*)d_in[11];
    const int* wsrc = (const int*)d_in[12];
    const int* wdst = (const int*)d_in[13];
    const int* csrc = (const int*)d_in[14];
    const int* cdst = (const int*)d_in[15];
    const int* esrc = (const int*)d_in[16];
    const int* edst = (const int*)d_in[17];
    float* out = (float*)d_out;

    int Na = in_sizes[0] / 128;
    int Np = in_sizes[1] / 128;
    int E  = in_sizes[12];
    int EL = in_sizes[16];

    float *xa0, *xa1, *xp0, *xp1, *mw, *mc, *ma, *blp;
    __nv_bfloat16 *wtH, *wtL;
    int *off_pw, *off_pc, *off_a, *col_pw, *col_pc, *col_a, *cnt, *cur;
    cudaGetSymbolAddress((void**)&xa0, g_xa0); cudaGetSymbolAddress((void**)&xa1, g_xa1);
    cudaGetSymbolAddress((void**)&xp0, g_xp0); cudaGetSymbolAddress((void**)&xp1, g_xp1);
    cudaGetSymbolAddress((void**)&mw, g_mw); cudaGetSymbolAddress((void**)&mc, g_mc);
    cudaGetSymbolAddress((void**)&ma, g_ma);
    cudaGetSymbolAddress((void**)&wtH, g_wtH); cudaGetSymbolAddress((void**)&wtL, g_wtL);
    cudaGetSymbolAddress((void**)&blp, g_blp);
    cudaGetSymbolAddress((void**)&off_pw, g_off_pw); cudaGetSymbolAddress((void**)&off_pc, g_off_pc);
    cudaGetSymbolAddress((void**)&off_a, g_off_a);
    cudaGetSymbolAddress((void**)&col_pw, g_col_pw); cudaGetSymbolAddress((void**)&col_pc, g_col_pc);
    cudaGetSymbolAddress((void**)&col_a, g_col_a);
    cudaGetSymbolAddress((void**)&cnt, g_cnt); cudaGetSymbolAddress((void**)&cur, g_cur);

    int egrid = (E + 255) / 256;

    // ---- CSR build ----
    cudaMemsetAsync(cnt, 0, Np * sizeof(int));
    count_kernel<<<egrid, 256>>>(wdst, E, cnt);
    scan_kernel<<<1, 1024>>>(cnt, off_pw, Np);
    cudaMemcpyAsync(cur, off_pw, Np * sizeof(int), cudaMemcpyDeviceToDevice);
    fill_kernel<<<egrid, 256>>>(wsrc, wdst, E, cur, col_pw);

    cudaMemsetAsync(cnt, 0, Np * sizeof(int));
    count_kernel<<<egrid, 256>>>(cdst, E, cnt);
    scan_kernel<<<1, 1024>>>(cnt, off_pc, Np);
    cudaMemcpyAsync(cur, off_pc, Np * sizeof(int), cudaMemcpyDeviceToDevice);
    fill_kernel<<<egrid, 256>>>(csrc, cdst, E, cur, col_pc);

    cudaMemsetAsync(cnt, 0, Na * sizeof(int));
    count_kernel<<<egrid, 256>>>(wsrc, E, cnt);
    scan_kernel<<<1, 1024>>>(cnt, off_a, Na);
    cudaMemcpyAsync(cur, off_a, Na * sizeof(int), cudaMemcpyDeviceToDevice);
    fill_kernel<<<egrid, 256>>>(wdst, wsrc, E, cur, col_a);

    // ---- weight transpose + split (slots: l*5 + {Wl0,Wl2,Wr0+Wr2,Wl1,Wr1}; 20,21 = dec) ----
    for (int l = 0; l < 4; l++) {
        int K = (l == 0) ? 128 : 256;
        const float *wl0, *wl1e, *wl2, *wr0, *wr1e, *wr2, *b0, *b2e;
        if (l == 0) {
            wl0 = Wl1; wl1e = Wl1 + 128 * 256; wl2 = Wl1 + 2 * 128 * 256;
            wr0 = Wr1; wr1e = Wr1 + 128 * 256; wr2 = Wr1 + 2 * 128 * 256;
            b0 = bl1; b2e = bl1 + 512;
        } else {
            int li = l - 1;
            wl0  = Wl + (size_t)(li * 3 + 0) * 65536;
            wl1e = Wl + (size_t)(li * 3 + 1) * 65536;
            wl2  = Wl + (size_t)(li * 3 + 2) * 65536;
            wr0  = Wr + (size_t)(li * 3 + 0) * 65536;
            wr1e = Wr + (size_t)(li * 3 + 1) * 65536;
            wr2  = Wr + (size_t)(li * 3 + 2) * 65536;
            b0   = bl + (size_t)(li * 3 + 0) * 256;
            b2e  = bl + (size_t)(li * 3 + 2) * 256;
        }
        int g = (256 * K + 255) / 256;
        int s = l * 5;
        wt_convert<<<g, 256>>>(wl0, (const float*)nullptr, K, wtH + (size_t)(s + 0) * WSTRIDE, wtL + (size_t)(s + 0) * WSTRIDE);
        wt_convert<<<g, 256>>>(wl2, (const float*)nullptr, K, wtH + (size_t)(s + 1) * WSTRIDE, wtL + (size_t)(s + 1) * WSTRIDE);
        wt_convert<<<g, 256>>>(wr0, wr2,                  K, wtH + (size_t)(s + 2) * WSTRIDE, wtL + (size_t)(s + 2) * WSTRIDE);
        wt_convert<<<g, 256>>>(wl1e, (const float*)nullptr, K, wtH + (size_t)(s + 3) * WSTRIDE, wtL + (size_t)(s + 3) * WSTRIDE);
        wt_convert<<<g, 256>>>(wr1e, (const float*)nullptr, K, wtH + (size_t)(s + 4) * WSTRIDE, wtL + (size_t)(s + 4) * WSTRIDE);
        bias_comb<<<1, 256>>>(b0, b2e, blp + l * 256);
    }
    wt_convert<<<256, 256>>>(dW1,             (const float*)nullptr, 256, wtH + (size_t)20 * WSTRIDE, wtL + (size_t)20 * WSTRIDE);
    wt_convert<<<256, 256>>>(dW1 + 256 * 256, (const float*)nullptr, 256, wtH + (size_t)21 * WSTRIDE, wtL + (size_t)21 * WSTRIDE);

    // ---- layers ----
    const float *ia = x_author, *ip = x_paper;
    float* outs_a[4] = { xa0, xa1, xa0, xa1 };
    float* outs_p[4] = { xp0, xp1, xp0, xp1 };
    dim3 gp((Np + 127) / 128, 2), ga((Na + 127) / 128, 2);
    for (int l = 0; l < 4; l++) {
        int K = (l == 0) ? 128 : 256;
        int agg_p = (Np + 7) / 8, agg_a = (Na + 7) / 8;
        if (K == 128) {
            aggregate_mean<128><<<agg_p, 256>>>(ia, off_pw, col_pw, mw, Np);
            aggregate_mean<128><<<agg_p, 256>>>(ip, off_pc, col_pc, mc, Np);
            aggregate_mean<128><<<agg_a, 256>>>(ip, off_a,  col_a,  ma, Na);
        } else {
            aggregate_mean<256><<<agg_p, 256>>>(ia, off_pw, col_pw, mw, Np);
            aggregate_mean<256><<<agg_p, 256>>>(ip, off_pc, col_pc, mc, Np);
            aggregate_mean<256><<<agg_a, 256>>>(ip, off_a,  col_a,  ma, Na);
        }
        int s = l * 5;
        const float* bias_a;
        if (l == 0) bias_a = bl1 + 256;
        else        bias_a = bl + (size_t)((l - 1) * 3 + 1) * 256;
        int relu = (l < 3) ? 1 : 0;
        gemm_mma<<<gp, 512>>>(3,
            mw, wtH + (size_t)(s + 0) * WSTRIDE, wtL + (size_t)(s + 0) * WSTRIDE,
            mc, wtH + (size_t)(s + 1) * WSTRIDE, wtL + (size_t)(s + 1) * WSTRIDE,
            ip, wtH + (size_t)(s + 2) * WSTRIDE, wtL + (size_t)(s + 2) * WSTRIDE,
            blp + l * 256, outs_p[l], Np, K, relu);
        gemm_mma<<<ga, 512>>>(2,
            ma, wtH + (size_t)(s + 3) * WSTRIDE, wtL + (size_t)(s + 3) * WSTRIDE,
            ia, wtH + (size_t)(s + 4) * WSTRIDE, wtL + (size_t)(s + 4) * WSTRIDE,
            (const float*)nullptr, (const __nv_bfloat16*)nullptr, (const __nv_bfloat16*)nullptr,
            bias_a, outs_a[l], Na, K, relu);
        ia = outs_a[l];
        ip = outs_p[l];
    }

    // ---- decoder ----
    init_out<<<(EL + 255) / 256, 256>>>(out, db2, EL);
    decoder_mma<<<dim3((EL + 127) / 128, 2), 512>>>(
        ia, esrc, edst,
        wtH + (size_t)20 * WSTRIDE, wtL + (size_t)20 * WSTRIDE,
        wtH + (size_t)21 * WSTRIDE, wtL + (size_t)21 * WSTRIDE,
        db1, dW2, out, EL);
}